// round 7
// baseline (speedup 1.0000x reference)
#include <cuda_runtime.h>
#include <cuda_bf16.h>
#include <math.h>
#include <stdint.h>

#define BSZ  128
#define NDIM 256
#define HDIM 1024
#define ALPHA 60.0f
#define BETA  20.0f
#define EPSC  1e-8f

typedef unsigned int uint;

// ---------------- scratch (allocation-free __device__ globals) ----------------
__device__ __align__(16) __nv_bfloat16 g_xh[BSZ * NDIM],      g_xl[BSZ * NDIM];
__device__ __align__(16) __nv_bfloat16 g_W1h[3][HDIM * NDIM], g_W1l[3][HDIM * NDIM];
__device__ __align__(16) __nv_bfloat16 g_W2h[3][NDIM * HDIM], g_W2l[3][NDIM * HDIM];
__device__ __align__(16) __nv_bfloat16 g_K2Th[HDIM * NDIM],   g_K2Tl[HDIM * NDIM]; // Wk2^T
__device__ __align__(16) __nv_bfloat16 g_K1Th[NDIM * HDIM],   g_K1Tl[NDIM * HDIM]; // Wk1^T
__device__ __align__(16) __nv_bfloat16 g_Hh[3][BSZ * HDIM],   g_Hl[3][BSZ * HDIM];
__device__ __align__(16) float         g_D[BSZ * HDIM];
__device__ __align__(16) float         g_fgk[3][BSZ * NDIM];
__device__ __align__(16) __nv_bfloat16 g_fgh[2][BSZ * NDIM],  g_fgl[2][BSZ * NDIM];
__device__ __align__(16) __nv_bfloat16 g_dvh[2][BSZ * HDIM],  g_dvl[2][BSZ * HDIM];
__device__ __align__(16) float         g_P2p[3][8][BSZ * NDIM];
__device__ __align__(16) float         g_P4p[2][8][BSZ * NDIM];

// ---------------- grid barrier ----------------
__device__ int g_cnt = 0, g_sense = 0;
__device__ __forceinline__ void gbar()
{
    __threadfence();
    __syncthreads();
    if (threadIdx.x == 0) {
        int s = *(volatile int*)&g_sense;
        int old = atomicAdd(&g_cnt, 1);
        if (old == (int)gridDim.x - 1) {
            atomicExch(&g_cnt, 0);
            __threadfence();
            atomicExch(&g_sense, 1 - s);
        } else {
            while (*(volatile int*)&g_sense == s) __nanosleep(64);
        }
        __threadfence();
    }
    __syncthreads();
}

// ---------------- bf16 split helpers ----------------
__device__ __forceinline__ void split_bf16(float v, __nv_bfloat16& h, __nv_bfloat16& l)
{
    h = __float2bfloat16(v);
    l = __float2bfloat16(v - __bfloat162float(h));
}
__device__ __forceinline__ void st_bf2(__nv_bfloat16* p, __nv_bfloat16 a, __nv_bfloat16 b)
{
    __nv_bfloat162 t; t.x = a; t.y = b;
    *reinterpret_cast<__nv_bfloat162*>(p) = t;
}

// ---------------- warp MMA: m16n8k16 bf16 -> f32, row.col ----------------
#define MMA16816(c, a, b) \
    asm volatile("mma.sync.aligned.m16n8k16.row.col.f32.bf16.bf16.f32 " \
        "{%0,%1,%2,%3}, {%4,%5,%6,%7}, {%8,%9}, {%0,%1,%2,%3};" \
        : "+f"((c)[0]), "+f"((c)[1]), "+f"((c)[2]), "+f"((c)[3]) \
        : "r"((a)[0]), "r"((a)[1]), "r"((a)[2]), "r"((a)[3]), \
          "r"((b)[0]), "r"((b)[1]))

__device__ __forceinline__ uint ldu32(const __nv_bfloat16* p)
{
    return *reinterpret_cast<const uint*>(p);
}

// ============================================================
// One 128x64 output tile:
//   D = (Ah+Al)[128,K] @ (Bh+Bl)[64,K]^T   (bf16x3, fp32 accum)
// 8 warps: 4(m) x 2(n); warp tile 32x32 (2 m-frags x 4 n-frags).
// Operands loaded directly from global (L1/L2-resident).
// EPI: epi(row, col, v0, v1) with col = even pair base (tile-local).
// ============================================================
template <class EPI>
__device__ void mma_tile(const __nv_bfloat16* __restrict__ Ah,
                         const __nv_bfloat16* __restrict__ Al, int lda,
                         const __nv_bfloat16* __restrict__ Bh,
                         const __nv_bfloat16* __restrict__ Bl, int ldb,
                         int K, const EPI& epi)
{
    const int w = threadIdx.x >> 5, lane = threadIdx.x & 31;
    const int g = lane >> 2, t = lane & 3;
    const int m0 = (w & 3) * 32;
    const int n0 = (w >> 2) * 32;

    float acc[2][4][4];
#pragma unroll
    for (int mi = 0; mi < 2; mi++)
#pragma unroll
        for (int nj = 0; nj < 4; nj++)
#pragma unroll
            for (int q = 0; q < 4; q++) acc[mi][nj][q] = 0.f;

    for (int k0 = 0; k0 < K; k0 += 16) {
        uint ah[2][4], al[2][4], bh[4][2], bl[4][2];
#pragma unroll
        for (int mi = 0; mi < 2; mi++) {
            const size_t ro = (size_t)(m0 + mi * 16 + g) * lda + k0 + t * 2;
            ah[mi][0] = ldu32(Ah + ro);
            ah[mi][1] = ldu32(Ah + ro + 8 * lda);
            ah[mi][2] = ldu32(Ah + ro + 8);
            ah[mi][3] = ldu32(Ah + ro + 8 * lda + 8);
            al[mi][0] = ldu32(Al + ro);
            al[mi][1] = ldu32(Al + ro + 8 * lda);
            al[mi][2] = ldu32(Al + ro + 8);
            al[mi][3] = ldu32(Al + ro + 8 * lda + 8);
        }
#pragma unroll
        for (int nj = 0; nj < 4; nj++) {
            const size_t ro = (size_t)(n0 + nj * 8 + g) * ldb + k0 + t * 2;
            bh[nj][0] = ldu32(Bh + ro);
            bh[nj][1] = ldu32(Bh + ro + 8);
            bl[nj][0] = ldu32(Bl + ro);
            bl[nj][1] = ldu32(Bl + ro + 8);
        }
#pragma unroll
        for (int mi = 0; mi < 2; mi++)
#pragma unroll
            for (int nj = 0; nj < 4; nj++) {
                MMA16816(acc[mi][nj], ah[mi], bh[nj]);
                MMA16816(acc[mi][nj], ah[mi], bl[nj]);
                MMA16816(acc[mi][nj], al[mi], bh[nj]);
            }
    }

#pragma unroll
    for (int mi = 0; mi < 2; mi++)
#pragma unroll
        for (int nj = 0; nj < 4; nj++) {
            const int row = m0 + mi * 16 + g;
            const int col = n0 + nj * 8 + t * 2;
            epi(row,     col, acc[mi][nj][0], acc[mi][nj][1]);
            epi(row + 8, col, acc[mi][nj][2], acc[mi][nj][3]);
        }
}

// ---------------- epilogues: epi(row, col(tile-local even), v0, v1) ----------------
struct EpiH {                  // H = tanh(acc + b1) -> bf16 h/l; optional D
    const float* b1; __nv_bfloat16 *Hh, *Hl; float* D; int nbase;
    __device__ __forceinline__ void operator()(int row, int col, float v0, float v1) const {
        const int c = nbase + col;
        float h0 = tanhf(v0 + b1[c]);
        float h1 = tanhf(v1 + b1[c + 1]);
        __nv_bfloat16 a0, l0, a1, l1;
        split_bf16(h0, a0, l0); split_bf16(h1, a1, l1);
        st_bf2(&Hh[row * HDIM + c], a0, a1);
        st_bf2(&Hl[row * HDIM + c], l0, l1);
        if (D)
            *reinterpret_cast<float2*>(&D[row * HDIM + c]) =
                make_float2(1.0f - h0 * h0, 1.0f - h1 * h1);
    }
};
struct EpiPart {               // raw fp32 partial, ld = 256
    float* P; int nbase;
    __device__ __forceinline__ void operator()(int row, int col, float v0, float v1) const {
        *reinterpret_cast<float2*>(&P[row * NDIM + nbase + col]) = make_float2(v0, v1);
    }
};
struct EpiDv {                 // dv = acc * D -> bf16 h/l
    const float* D; __nv_bfloat16 *Vh, *Vl; int nbase;
    __device__ __forceinline__ void operator()(int row, int col, float v0, float v1) const {
        const int c = nbase + col;
        const float2 dd = *reinterpret_cast<const float2*>(&D[row * HDIM + c]);
        float w0 = v0 * dd.x, w1 = v1 * dd.y;
        __nv_bfloat16 a0, l0, a1, l1;
        split_bf16(w0, a0, l0); split_bf16(w1, a1, l1);
        st_bf2(&Vh[row * HDIM + c], a0, a1);
        st_bf2(&Vl[row * HDIM + c], l0, l1);
    }
};

// ---------------- conversion / transpose helpers ----------------
__device__ void cvt_arr(const float* __restrict__ s, __nv_bfloat16* h,
                        __nv_bfloat16* l, int n4, int gtid, int gsz)
{
    for (int i = gtid; i < n4; i += gsz) {
        float4 v = reinterpret_cast<const float4*>(s)[i];
        __nv_bfloat16 h0, l0, h1, l1, h2, l2, h3, l3;
        split_bf16(v.x, h0, l0); split_bf16(v.y, h1, l1);
        split_bf16(v.z, h2, l2); split_bf16(v.w, h3, l3);
        st_bf2(&h[4 * i], h0, h1); st_bf2(&h[4 * i + 2], h2, h3);
        st_bf2(&l[4 * i], l0, l1); st_bf2(&l[4 * i + 2], l2, l3);
    }
}
// transpose 64x64 fp32 tile src[r0..][c0..] -> dst[c][r] as bf16 hi/lo
__device__ void trans_tile(float (&ts)[64][65], const float* __restrict__ src, int lds,
                           int r0, int c0, __nv_bfloat16* dh, __nv_bfloat16* dl, int ldd)
{
    const int tid = threadIdx.x;
    __syncthreads();
    for (int i = tid; i < 4096; i += 256) {
        int r = i >> 6, c = i & 63;
        ts[r][c] = src[(size_t)(r0 + r) * lds + c0 + c];
    }
    __syncthreads();
    for (int i = tid; i < 4096; i += 256) {
        int dr = i >> 6, dc = i & 63;
        float v = ts[dc][dr];
        __nv_bfloat16 h, l;
        split_bf16(v, h, l);
        dh[(size_t)(c0 + dr) * ldd + r0 + dc] = h;
        dl[(size_t)(c0 + dr) * ldd + r0 + dc] = l;
    }
}

// ---------------- persistent fused kernel ----------------
__global__ __launch_bounds__(256, 2) void fused_mma_kernel(
    const float* __restrict__ x,
    const float* __restrict__ Wf1, const float* __restrict__ bf1,
    const float* __restrict__ Wf2, const float* __restrict__ bf2,
    const float* __restrict__ Wg1, const float* __restrict__ bg1,
    const float* __restrict__ Wg2, const float* __restrict__ bg2,
    const float* __restrict__ Wk1, const float* __restrict__ bk1,
    const float* __restrict__ Wk2, const float* __restrict__ bk2,
    float* __restrict__ out)
{
    __shared__ float ts[64][65];
    const int tid = threadIdx.x;
    const int bid = blockIdx.x;
    const int gtid = bid * 256 + tid;
    const int gsz = gridDim.x * 256;

    // ---------- Ph0: convert inputs to bf16 hi/lo; transpose Wk1, Wk2 ----------
    cvt_arr(x,   g_xh,     g_xl,     BSZ * NDIM / 4,  gtid, gsz);
    cvt_arr(Wf1, g_W1h[0], g_W1l[0], HDIM * NDIM / 4, gtid, gsz);
    cvt_arr(Wg1, g_W1h[1], g_W1l[1], HDIM * NDIM / 4, gtid, gsz);
    cvt_arr(Wk1, g_W1h[2], g_W1l[2], HDIM * NDIM / 4, gtid, gsz);
    cvt_arr(Wf2, g_W2h[0], g_W2l[0], NDIM * HDIM / 4, gtid, gsz);
    cvt_arr(Wg2, g_W2h[1], g_W2l[1], NDIM * HDIM / 4, gtid, gsz);
    cvt_arr(Wk2, g_W2h[2], g_W2l[2], NDIM * HDIM / 4, gtid, gsz);
    for (int t = bid; t < 128; t += gridDim.x) {
        if (t < 64) {   // Wk1 [1024,256] -> K1T [256,1024]
            trans_tile(ts, Wk1, NDIM, (t >> 2) * 64, (t & 3) * 64, g_K1Th, g_K1Tl, HDIM);
        } else {        // Wk2 [256,1024] -> K2T [1024,256]
            int tt = t - 64;
            trans_tile(ts, Wk2, HDIM, (tt & 3) * 64, (tt >> 2) * 64, g_K2Th, g_K2Tl, NDIM);
        }
    }
    gbar();

    // ---------- Ph1: H[z] = tanh(x @ W1[z]^T + b1); 48 tiles, K=256 ----------
    for (int t = bid; t < 48; t += gridDim.x) {
        const int z = t >> 4, n = t & 15;
        const float* b1 = (z == 0) ? bf1 : (z == 1) ? bg1 : bk1;
        EpiH epi{b1, g_Hh[z], g_Hl[z], (z == 2) ? g_D : (float*)nullptr, n * 64};
        mma_tile(g_xh, g_xl, NDIM,
                 g_W1h[z] + (size_t)n * 64 * NDIM, g_W1l[z] + (size_t)n * 64 * NDIM,
                 NDIM, NDIM, epi);
    }
    gbar();

    // ---------- Ph2: p2[z][s] = H[z][:,s*128:+128] @ W2[z]^T chunk; 96 tiles ----------
    for (int t = bid; t < 96; t += gridDim.x) {
        const int z = t / 32, r = t % 32;
        const int n = r >> 3, s = r & 7;
        EpiPart epi{g_P2p[z][s], n * 64};
        mma_tile(g_Hh[z] + s * 128, g_Hl[z] + s * 128, HDIM,
                 g_W2h[z] + (size_t)n * 64 * HDIM + s * 128,
                 g_W2l[z] + (size_t)n * 64 * HDIM + s * 128,
                 HDIM, 128, epi);
    }
    gbar();

    // ---------- Ph2b: f,g,k = sum8 p2 + b2; f,g also bf16 h/l ----------
    for (int i4 = gtid; i4 < 3 * (BSZ * NDIM / 4); i4 += gsz) {
        const int z = i4 / (BSZ * NDIM / 4);
        const int j = i4 - z * (BSZ * NDIM / 4);
        const int col4 = j & (NDIM / 4 - 1);
        const float* b2 = (z == 0) ? bf2 : (z == 1) ? bg2 : bk2;
        float4 s = reinterpret_cast<const float4*>(b2)[col4];
#pragma unroll
        for (int p = 0; p < 8; p++) {
            float4 v = reinterpret_cast<const float4*>(g_P2p[z][p])[j];
            s.x += v.x; s.y += v.y; s.z += v.z; s.w += v.w;
        }
        reinterpret_cast<float4*>(g_fgk[z])[j] = s;
        if (z < 2) {
            __nv_bfloat16 h0, l0, h1, l1, h2, l2, h3, l3;
            split_bf16(s.x, h0, l0); split_bf16(s.y, h1, l1);
            split_bf16(s.z, h2, l2); split_bf16(s.w, h3, l3);
            st_bf2(&g_fgh[z][4 * j], h0, h1); st_bf2(&g_fgh[z][4 * j + 2], h2, h3);
            st_bf2(&g_fgl[z][4 * j], l0, l1); st_bf2(&g_fgl[z][4 * j + 2], l2, l3);
        }
    }
    gbar();

    // ---------- Ph3: dv[z] = ({f,g} @ K2T^T) * D; 32 tiles, K=256 ----------
    for (int t = bid; t < 32; t += gridDim.x) {
        const int z = t >> 4, n = t & 15;
        EpiDv epi{g_D, g_dvh[z], g_dvl[z], n * 64};
        mma_tile(g_fgh[z], g_fgl[z], NDIM,
                 g_K2Th + (size_t)n * 64 * NDIM, g_K2Tl + (size_t)n * 64 * NDIM,
                 NDIM, NDIM, epi);
    }
    gbar();

    // ---------- Ph4: p4[z][s] = dv[z] chunk @ K1T^T chunk; 64 tiles, K=128 ----------
    for (int t = bid; t < 64; t += gridDim.x) {
        const int z = t / 32, r = t % 32;
        const int n = r >> 3, s = r & 7;
        EpiPart epi{g_P4p[z][s], n * 64};
        mma_tile(g_dvh[z] + s * 128, g_dvl[z] + s * 128, HDIM,
                 g_K1Th + (size_t)n * 64 * HDIM + s * 128,
                 g_K1Tl + (size_t)n * 64 * HDIM + s * 128,
                 HDIM, 128, epi);
    }
    gbar();

    // ---------- Ph5: reduce + norms + mask + output ----------
    if (bid < BSZ) {
        const int b = bid, i = tid;
        const int idx = b * NDIM + i;
        float jfv = 0.f, jgv = 0.f;
#pragma unroll
        for (int s = 0; s < 8; s++) {
            jfv += g_P4p[0][s][idx];
            jgv += g_P4p[1][s][idx];
        }
        const float fv = g_fgk[0][idx];
        const float gv = g_fgk[1][idx];
        const float kv = g_fgk[2][idx];

        float kn2 = kv * kv, jf2 = jfv * jfv, dt = kv * jgv;
#pragma unroll
        for (int off = 16; off > 0; off >>= 1) {
            kn2 += __shfl_down_sync(0xffffffffu, kn2, off);
            jf2 += __shfl_down_sync(0xffffffffu, jf2, off);
            dt  += __shfl_down_sync(0xffffffffu, dt,  off);
        }
        __shared__ float s_kn2[8], s_jf2[8], s_dt[8], s_scale;
        const int warp = i >> 5, lane = i & 31;
        if (lane == 0) { s_kn2[warp] = kn2; s_jf2[warp] = jf2; s_dt[warp] = dt; }
        __syncthreads();
        if (i == 0) {
            float tkn2 = 0.f, tjf2 = 0.f, tdt = 0.f;
#pragma unroll
            for (int ww = 0; ww < 8; ww++) {
                tkn2 += s_kn2[ww]; tjf2 += s_jf2[ww]; tdt += s_dt[ww];
            }
            const float kn   = sqrtf(tkn2);
            const float kn9  = tkn2 * tkn2 * tkn2 * tkn2 * kn;
            const float kn10 = kn9 * kn;
            const float c1 = sqrtf(tjf2) - ALPHA * kn9;
            const float c2 = tdt - BETA * kn10;
            s_scale = ((c1 > EPSC) || (c2 < -EPSC)) ? 0.5f : 1.0f;
        }
        __syncthreads();
        out[idx] = s_scale * (fv + gv);
    }
}

// inputs: 0:t 1:x 2:Wf1 3:bf1 4:Wf2 5:bf2 6:Wg1 7:bg1 8:Wg2 9:bg2 10:Wk1 11:bk1 12:Wk2 13:bk2
extern "C" void kernel_launch(void* const* d_in, const int* in_sizes, int n_in,
                              void* d_out, int out_size)
{
    const float* x   = (const float*)d_in[1];
    const float* Wf1 = (const float*)d_in[2];
    const float* bf1 = (const float*)d_in[3];
    const float* Wf2 = (const float*)d_in[4];
    const float* bf2 = (const float*)d_in[5];
    const float* Wg1 = (const float*)d_in[6];
    const float* bg1 = (const float*)d_in[7];
    const float* Wg2 = (const float*)d_in[8];
    const float* bg2 = (const float*)d_in[9];
    const float* Wk1 = (const float*)d_in[10];
    const float* bk1 = (const float*)d_in[11];
    const float* Wk2 = (const float*)d_in[12];
    const float* bk2 = (const float*)d_in[13];
    float* out = (float*)d_out;

    int dev = 0, sms = 148;
    cudaGetDevice(&dev);
    cudaDeviceGetAttribute(&sms, cudaDevAttrMultiProcessorCount, dev);
    int occ = 1;
    cudaOccupancyMaxActiveBlocksPerMultiprocessor(&occ, fused_mma_kernel, 256, 0);
    if (occ < 1) occ = 1;
    if (occ > 2) occ = 2;
    const int grid = sms * occ;     // all co-resident -> grid barrier safe

    fused_mma_kernel<<<grid, 256>>>(x, Wf1, bf1, Wf2, bf2, Wg1, bg1, Wg2, bg2,
                                    Wk1, bk1, Wk2, bk2, out);
}

// round 8
// speedup vs baseline: 1.7502x; 1.7502x over previous
#include <cuda_runtime.h>
#include <cuda_bf16.h>
#include <math.h>
#include <stdint.h>

#define BSZ  128
#define NDIM 256
#define HDIM 1024
#define ALPHA 60.0f
#define BETA  20.0f
#define EPSC  1e-8f

typedef unsigned int uint;

// ---------------- scratch (allocation-free __device__ globals) ----------------
__device__ __align__(16) __nv_bfloat16 g_xh[BSZ * NDIM],      g_xl[BSZ * NDIM];
__device__ __align__(16) __nv_bfloat16 g_W1h[3][HDIM * NDIM], g_W1l[3][HDIM * NDIM];
__device__ __align__(16) __nv_bfloat16 g_W2h[3][NDIM * HDIM], g_W2l[3][NDIM * HDIM];
__device__ __align__(16) __nv_bfloat16 g_K2Th[HDIM * NDIM],   g_K2Tl[HDIM * NDIM]; // Wk2^T [1024,256]
__device__ __align__(16) __nv_bfloat16 g_K1Th[NDIM * HDIM],   g_K1Tl[NDIM * HDIM]; // Wk1^T [256,1024]
__device__ __align__(16) __nv_bfloat16 g_Hh[3][BSZ * HDIM],   g_Hl[3][BSZ * HDIM];
__device__ __align__(16) float         g_D[BSZ * HDIM];
__device__ __align__(16) float         g_fgk[3][BSZ * NDIM];
__device__ __align__(16) __nv_bfloat16 g_fgh[2][BSZ * NDIM],  g_fgl[2][BSZ * NDIM];
__device__ __align__(16) __nv_bfloat16 g_dvh[2][BSZ * HDIM],  g_dvl[2][BSZ * HDIM];
__device__ __align__(16) float         g_P1p[3][2][BSZ * HDIM];
__device__ __align__(16) float         g_P2p[3][8][BSZ * NDIM];
__device__ __align__(16) float         g_P3p[2][2][BSZ * HDIM];
__device__ __align__(16) float         g_P4p[2][8][BSZ * NDIM];

// ---------------- grid barrier ----------------
__device__ int g_cnt = 0, g_sense = 0;
__device__ __forceinline__ void gbar()
{
    __threadfence();
    __syncthreads();
    if (threadIdx.x == 0) {
        int s = *(volatile int*)&g_sense;
        int old = atomicAdd(&g_cnt, 1);
        if (old == (int)gridDim.x - 1) {
            atomicExch(&g_cnt, 0);
            __threadfence();
            atomicExch(&g_sense, 1 - s);
        } else {
            while (*(volatile int*)&g_sense == s) __nanosleep(64);
        }
        __threadfence();
    }
    __syncthreads();
}

// ---------------- helpers ----------------
__device__ __forceinline__ uint smem_u32(const void* p)
{
    uint a;
    asm("{ .reg .u64 t; cvta.to.shared.u64 t, %1; cvt.u32.u64 %0, t; }"
        : "=r"(a) : "l"(p));
    return a;
}
__device__ __forceinline__ void split_bf16(float v, __nv_bfloat16& h, __nv_bfloat16& l)
{
    h = __float2bfloat16(v);
    l = __float2bfloat16(v - __bfloat162float(h));
}
__device__ __forceinline__ void st_bf2(__nv_bfloat16* p, __nv_bfloat16 a, __nv_bfloat16 b)
{
    __nv_bfloat162 t; t.x = a; t.y = b;
    *reinterpret_cast<__nv_bfloat162*>(p) = t;
}

#define CP16(dst, src) \
    asm volatile("cp.async.cg.shared.global [%0], [%1], 16;" :: "r"(dst), "l"(src))
#define CP_COMMIT() asm volatile("cp.async.commit_group;" ::: "memory")
#define CP_WAIT(n)  asm volatile("cp.async.wait_group %0;" :: "n"(n) : "memory")

#define LDM4(r, addr) \
    asm volatile("ldmatrix.sync.aligned.m8n8.x4.shared.b16 {%0,%1,%2,%3}, [%4];" \
        : "=r"((r)[0]), "=r"((r)[1]), "=r"((r)[2]), "=r"((r)[3]) : "r"(addr))

#define MMA16816(c, a, b0, b1) \
    asm volatile("mma.sync.aligned.m16n8k16.row.col.f32.bf16.bf16.f32 " \
        "{%0,%1,%2,%3}, {%4,%5,%6,%7}, {%8,%9}, {%0,%1,%2,%3};" \
        : "+f"((c)[0]), "+f"((c)[1]), "+f"((c)[2]), "+f"((c)[3]) \
        : "r"((a)[0]), "r"((a)[1]), "r"((a)[2]), "r"((a)[3]), "r"(b0), "r"(b1))

// ---------------- smem buffer layout (per 48KB buffer) ----------------
// Ah [0,16K) Al [16K,32K) Bh [32K,40K) Bl [40K,48K); rows = 128B, swizzle u^(row&7)
#define BUF_AL 16384
#define BUF_BH 32768
#define BUF_BL 40960
#define BUF_SZ 49152
#define SMEM_TOTAL (2 * BUF_SZ)

struct Job {
    const __nv_bfloat16 *Ah, *Al, *Bh, *Bl;
    int lda, ldb, k0;
    float* O; int ldo;
};

// fill one K=64 chunk (A 128 rows, B 64 rows) into buffer at smem addr `buf`
__device__ __forceinline__ void fill_chunk(uint buf, const Job& j, int kc)
{
    const int tid = threadIdx.x;
#pragma unroll
    for (int i = 0; i < 4; i++) {
        const int idx = tid + i * 256;          // 0..1023
        const int row = idx >> 3, u = idx & 7;
        const uint sw = (uint)row * 128 + (uint)((u ^ (row & 7)) * 16);
        const size_t go = (size_t)row * j.lda + kc + u * 8;
        CP16(buf + sw,          j.Ah + go);
        CP16(buf + BUF_AL + sw, j.Al + go);
    }
#pragma unroll
    for (int i = 0; i < 2; i++) {
        const int idx = tid + i * 256;          // 0..511
        const int row = idx >> 3, u = idx & 7;
        const uint sw = (uint)row * 128 + (uint)((u ^ (row & 7)) * 16);
        const size_t go = (size_t)row * j.ldb + kc + u * 8;
        CP16(buf + BUF_BH + sw, j.Bh + go);
        CP16(buf + BUF_BL + sw, j.Bl + go);
    }
    CP_COMMIT();
}

// compute one K=64 chunk from buffer into acc (bf16x3: AhBh + AhBl + AlBh)
__device__ __forceinline__ void compute_chunk(uint buf, float acc[2][4][4])
{
    const int lane = threadIdx.x & 31;
    const int w = threadIdx.x >> 5;
    const int m0w = (w & 3) * 32;
    const int n0w = (w >> 2) * 32;

    // A lane address pieces: row = m0w + mi*16 + (lane&15); u = ks*2 + (lane>>4)
    const int arow_l = lane & 15;
    const int au_l   = lane >> 4;
    // B: row = n0w + njp*16 + (lane&7) + ((lane>>4)&1)*8; u = ks*2 + ((lane>>3)&1)
    const int brow_l = (lane & 7) + ((lane >> 4) & 1) * 8;
    const int bu_l   = (lane >> 3) & 1;

#pragma unroll
    for (int ks = 0; ks < 4; ks++) {
        uint ah[2][4], al[2][4], bh[2][4], bl[2][4];
#pragma unroll
        for (int mi = 0; mi < 2; mi++) {
            const int r = m0w + mi * 16 + arow_l;
            const int u = ks * 2 + au_l;
            const uint ad = buf + (uint)r * 128 + (uint)((u ^ (r & 7)) * 16);
            LDM4(ah[mi], ad);
            LDM4(al[mi], ad + BUF_AL);
        }
#pragma unroll
        for (int njp = 0; njp < 2; njp++) {
            const int r = n0w + njp * 16 + brow_l;
            const int u = ks * 2 + bu_l;
            const uint bd = buf + BUF_BH + (uint)r * 128 + (uint)((u ^ (r & 7)) * 16);
            LDM4(bh[njp], bd);
            LDM4(bl[njp], bd + (BUF_BL - BUF_BH));
        }
#pragma unroll
        for (int mi = 0; mi < 2; mi++)
#pragma unroll
            for (int njp = 0; njp < 2; njp++)
#pragma unroll
                for (int h = 0; h < 2; h++) {
                    float* c = acc[mi][njp * 2 + h];
                    MMA16816(c, ah[mi], bh[njp][2 * h], bh[njp][2 * h + 1]);
                    MMA16816(c, ah[mi], bl[njp][2 * h], bl[njp][2 * h + 1]);
                    MMA16816(c, al[mi], bh[njp][2 * h], bh[njp][2 * h + 1]);
                }
    }
}

__device__ __forceinline__ void store_tile(const Job& j, const float acc[2][4][4])
{
    const int lane = threadIdx.x & 31;
    const int w = threadIdx.x >> 5;
    const int g = lane >> 2, t = lane & 3;
    const int m0w = (w & 3) * 32, n0w = (w >> 2) * 32;
#pragma unroll
    for (int mi = 0; mi < 2; mi++)
#pragma unroll
        for (int nj = 0; nj < 4; nj++) {
            const int r = m0w + mi * 16 + g, c = n0w + nj * 8 + t * 2;
            *reinterpret_cast<float2*>(&j.O[(size_t)r * j.ldo + c]) =
                make_float2(acc[mi][nj][0], acc[mi][nj][1]);
            *reinterpret_cast<float2*>(&j.O[(size_t)(r + 8) * j.ldo + c]) =
                make_float2(acc[mi][nj][2], acc[mi][nj][3]);
        }
}

// phase driver: static unit assignment, cross-chunk cp.async double buffering
template <class DEC>
__device__ void gemm_phase(uint sb, int U, const DEC& dec)
{
    const int G = gridDim.x;
    int u = blockIdx.x;
    const uint buf0 = sb, buf1 = sb + BUF_SZ;

    Job j;
    if (u < U) {
        dec(u, j);
        fill_chunk(buf0, j, j.k0);
        fill_chunk(buf1, j, j.k0 + 64);
    }
    while (u < U) {
        const int un = u + G;
        Job jn;
        if (un < U) dec(un, jn);

        float acc[2][4][4];
#pragma unroll
        for (int a = 0; a < 2; a++)
#pragma unroll
            for (int b = 0; b < 4; b++)
#pragma unroll
                for (int q = 0; q < 4; q++) acc[a][b][q] = 0.f;

        CP_WAIT(1);
        __syncthreads();
        compute_chunk(buf0, acc);
        __syncthreads();
        if (un < U) {
            fill_chunk(buf0, jn, jn.k0);
            CP_WAIT(1);
        } else {
            CP_WAIT(0);
        }
        __syncthreads();
        compute_chunk(buf1, acc);
        store_tile(j, acc);
        __syncthreads();
        if (un < U) fill_chunk(buf1, jn, jn.k0 + 64);
        u = un;
        j = jn;
    }
}

// ---------------- phase decoders (all units: 128x64 tile, K=128) ----------------
struct DecP1 {      // U=96: z3 x n16 x s2; A=x[128,256], B=W1[z] rows n*64
    __device__ void operator()(int u, Job& j) const {
        const int z = u >> 5, r = u & 31, n = r >> 1, s = r & 1;
        j.Ah = g_xh; j.Al = g_xl; j.lda = NDIM;
        j.Bh = g_W1h[z] + (size_t)n * 64 * NDIM;
        j.Bl = g_W1l[z] + (size_t)n * 64 * NDIM; j.ldb = NDIM;
        j.k0 = s * 128;
        j.O = g_P1p[z][s] + n * 64; j.ldo = HDIM;
    }
};
struct DecP2 {      // U=96: z3 x n4 x s8; A=H[z][128,1024], B=W2[z]
    __device__ void operator()(int u, Job& j) const {
        const int z = u >> 5, r = u & 31, n = r >> 3, s = r & 7;
        j.Ah = g_Hh[z]; j.Al = g_Hl[z]; j.lda = HDIM;
        j.Bh = g_W2h[z] + (size_t)n * 64 * HDIM;
        j.Bl = g_W2l[z] + (size_t)n * 64 * HDIM; j.ldb = HDIM;
        j.k0 = s * 128;
        j.O = g_P2p[z][s] + n * 64; j.ldo = NDIM;
    }
};
struct DecP3 {      // U=64: z2 x n16 x s2; A=fg[z][128,256], B=K2T[1024,256]
    __device__ void operator()(int u, Job& j) const {
        const int z = u >> 5, r = u & 31, n = r >> 1, s = r & 1;
        j.Ah = g_fgh[z]; j.Al = g_fgl[z]; j.lda = NDIM;
        j.Bh = g_K2Th + (size_t)n * 64 * NDIM;
        j.Bl = g_K2Tl + (size_t)n * 64 * NDIM; j.ldb = NDIM;
        j.k0 = s * 128;
        j.O = g_P3p[z][s] + n * 64; j.ldo = HDIM;
    }
};
struct DecP4 {      // U=64: z2 x n4 x s8; A=dv[z][128,1024], B=K1T[256,1024]
    __device__ void operator()(int u, Job& j) const {
        const int z = u >> 5, r = u & 31, n = r >> 3, s = r & 7;
        j.Ah = g_dvh[z]; j.Al = g_dvl[z]; j.lda = HDIM;
        j.Bh = g_K1Th + (size_t)n * 64 * HDIM;
        j.Bl = g_K1Tl + (size_t)n * 64 * HDIM; j.ldb = HDIM;
        j.k0 = s * 128;
        j.O = g_P4p[z][s] + n * 64; j.ldo = NDIM;
    }
};

// ---------------- conversion / transpose ----------------
__device__ void cvt_arr(const float* __restrict__ s, __nv_bfloat16* h,
                        __nv_bfloat16* l, int n4, int gtid, int gsz)
{
    for (int i = gtid; i < n4; i += gsz) {
        float4 v = reinterpret_cast<const float4*>(s)[i];
        __nv_bfloat16 h0, l0, h1, l1, h2, l2, h3, l3;
        split_bf16(v.x, h0, l0); split_bf16(v.y, h1, l1);
        split_bf16(v.z, h2, l2); split_bf16(v.w, h3, l3);
        st_bf2(&h[4 * i], h0, h1); st_bf2(&h[4 * i + 2], h2, h3);
        st_bf2(&l[4 * i], l0, l1); st_bf2(&l[4 * i + 2], l2, l3);
    }
}
__device__ void trans_tile(float (*ts)[65], const float* __restrict__ src, int lds,
                           int r0, int c0, __nv_bfloat16* dh, __nv_bfloat16* dl, int ldd)
{
    const int tid = threadIdx.x;
    __syncthreads();
    for (int i = tid; i < 4096; i += 256) {
        const int r = i >> 6, c = i & 63;
        ts[r][c] = src[(size_t)(r0 + r) * lds + c0 + c];
    }
    __syncthreads();
    for (int i = tid; i < 4096; i += 256) {
        const int dr = i >> 6, dc = i & 63;
        __nv_bfloat16 h, l;
        split_bf16(ts[dc][dr], h, l);
        dh[(size_t)(c0 + dr) * ldd + r0 + dc] = h;
        dl[(size_t)(c0 + dr) * ldd + r0 + dc] = l;
    }
}

// ---------------- persistent fused kernel ----------------
__global__ __launch_bounds__(256, 2) void fused_mma_kernel(
    const float* __restrict__ x,
    const float* __restrict__ Wf1, const float* __restrict__ bf1,
    const float* __restrict__ Wf2, const float* __restrict__ bf2,
    const float* __restrict__ Wg1, const float* __restrict__ bg1,
    const float* __restrict__ Wg2, const float* __restrict__ bg2,
    const float* __restrict__ Wk1, const float* __restrict__ bk1,
    const float* __restrict__ Wk2, const float* __restrict__ bk2,
    float* __restrict__ out)
{
    extern __shared__ char smem[];
    const uint sb = smem_u32(smem);
    const int tid = threadIdx.x;
    const int bid = blockIdx.x;
    const int gtid = bid * 256 + tid;
    const int gsz = gridDim.x * 256;

    // ---------- Ph0: convert to bf16 hi/lo; transpose Wk1, Wk2 ----------
    cvt_arr(x,   g_xh,     g_xl,     BSZ * NDIM / 4,  gtid, gsz);
    cvt_arr(Wf1, g_W1h[0], g_W1l[0], HDIM * NDIM / 4, gtid, gsz);
    cvt_arr(Wg1, g_W1h[1], g_W1l[1], HDIM * NDIM / 4, gtid, gsz);
    cvt_arr(Wk1, g_W1h[2], g_W1l[2], HDIM * NDIM / 4, gtid, gsz);
    cvt_arr(Wf2, g_W2h[0], g_W2l[0], NDIM * HDIM / 4, gtid, gsz);
    cvt_arr(Wg2, g_W2h[1], g_W2l[1], NDIM * HDIM / 4, gtid, gsz);
    cvt_arr(Wk2, g_W2h[2], g_W2l[2], NDIM * HDIM / 4, gtid, gsz);
    {
        float (*ts)[65] = reinterpret_cast<float(*)[65]>(smem);
        for (int t = bid; t < 128; t += gridDim.x) {
            if (t < 64)
                trans_tile(ts, Wk1, NDIM, (t >> 2) * 64, (t & 3) * 64, g_K1Th, g_K1Tl, HDIM);
            else {
                const int tt = t - 64;
                trans_tile(ts, Wk2, HDIM, (tt & 3) * 64, (tt >> 2) * 64, g_K2Th, g_K2Tl, NDIM);
            }
        }
    }
    gbar();

    // ---------- Ph1: P1p partials ----------
    gemm_phase(sb, 96, DecP1{});
    gbar();

    // ---------- Ph1b: H = tanh(sum2 + b1) -> bf16 h/l; D for k ----------
    {
        const int PER = BSZ * HDIM / 4;
        for (int i4 = gtid; i4 < 3 * PER; i4 += gsz) {
            const int z = i4 / PER, j = i4 - z * PER;
            const int col4 = j & (HDIM / 4 - 1);
            const float* b1 = (z == 0) ? bf1 : (z == 1) ? bg1 : bk1;
            float4 a = reinterpret_cast<const float4*>(g_P1p[z][0])[j];
            float4 b = reinterpret_cast<const float4*>(g_P1p[z][1])[j];
            float4 bb = reinterpret_cast<const float4*>(b1)[col4];
            float h0 = tanhf(a.x + b.x + bb.x);
            float h1 = tanhf(a.y + b.y + bb.y);
            float h2 = tanhf(a.z + b.z + bb.z);
            float h3 = tanhf(a.w + b.w + bb.w);
            __nv_bfloat16 p0, q0, p1, q1, p2, q2, p3, q3;
            split_bf16(h0, p0, q0); split_bf16(h1, p1, q1);
            split_bf16(h2, p2, q2); split_bf16(h3, p3, q3);
            st_bf2(&g_Hh[z][4 * j], p0, p1); st_bf2(&g_Hh[z][4 * j + 2], p2, p3);
            st_bf2(&g_Hl[z][4 * j], q0, q1); st_bf2(&g_Hl[z][4 * j + 2], q2, q3);
            if (z == 2)
                reinterpret_cast<float4*>(g_D)[j] =
                    make_float4(1.f - h0 * h0, 1.f - h1 * h1, 1.f - h2 * h2, 1.f - h3 * h3);
        }
    }
    gbar();

    // ---------- Ph2: P2p partials ----------
    gemm_phase(sb, 96, DecP2{});
    gbar();

    // ---------- Ph2b: f,g,k = sum8 + b2; f,g -> bf16 h/l ----------
    {
        const int PER = BSZ * NDIM / 4;
        for (int i4 = gtid; i4 < 3 * PER; i4 += gsz) {
            const int z = i4 / PER, j = i4 - z * PER;
            const int col4 = j & (NDIM / 4 - 1);
            const float* b2 = (z == 0) ? bf2 : (z == 1) ? bg2 : bk2;
            float4 s = reinterpret_cast<const float4*>(b2)[col4];
#pragma unroll
            for (int p = 0; p < 8; p++) {
                float4 v = reinterpret_cast<const float4*>(g_P2p[z][p])[j];
                s.x += v.x; s.y += v.y; s.z += v.z; s.w += v.w;
            }
            reinterpret_cast<float4*>(g_fgk[z])[j] = s;
            if (z < 2) {
                __nv_bfloat16 p0, q0, p1, q1, p2, q2, p3, q3;
                split_bf16(s.x, p0, q0); split_bf16(s.y, p1, q1);
                split_bf16(s.z, p2, q2); split_bf16(s.w, p3, q3);
                st_bf2(&g_fgh[z][4 * j], p0, p1); st_bf2(&g_fgh[z][4 * j + 2], p2, p3);
                st_bf2(&g_fgl[z][4 * j], q0, q1); st_bf2(&g_fgl[z][4 * j + 2], q2, q3);
            }
        }
    }
    gbar();

    // ---------- Ph3: P3p partials ----------
    gemm_phase(sb, 64, DecP3{});
    gbar();

    // ---------- Ph3b: dv = (sum2) * D -> bf16 h/l ----------
    {
        const int PER = BSZ * HDIM / 4;
        for (int i4 = gtid; i4 < 2 * PER; i4 += gsz) {
            const int z = i4 / PER, j = i4 - z * PER;
            float4 a = reinterpret_cast<const float4*>(g_P3p[z][0])[j];
            float4 b = reinterpret_cast<const float4*>(g_P3p[z][1])[j];
            float4 d = reinterpret_cast<const float4*>(g_D)[j];
            float v0 = (a.x + b.x) * d.x, v1 = (a.y + b.y) * d.y;
            float v2 = (a.z + b.z) * d.z, v3 = (a.w + b.w) * d.w;
            __nv_bfloat16 p0, q0, p1, q1, p2, q2, p3, q3;
            split_bf16(v0, p0, q0); split_bf16(v1, p1, q1);
            split_bf16(v2, p2, q2); split_bf16(v3, p3, q3);
            st_bf2(&g_dvh[z][4 * j], p0, p1); st_bf2(&g_dvh[z][4 * j + 2], p2, p3);
            st_bf2(&g_dvl[z][4 * j], q0, q1); st_bf2(&g_dvl[z][4 * j + 2], q2, q3);
        }
    }
    gbar();

    // ---------- Ph4: P4p partials ----------
    gemm_phase(sb, 64, DecP4{});
    gbar();

    // ---------- Ph5: reduce + norms + mask + output ----------
    if (bid < BSZ) {
        const int b = bid, i = tid;
        const int idx = b * NDIM + i;
        float jfv = 0.f, jgv = 0.f;
#pragma unroll
        for (int s = 0; s < 8; s++) {
            jfv += g_P4p[0][s][idx];
            jgv += g_P4p[1][s][idx];
        }
        const float fv = g_fgk[0][idx];
        const float gv = g_fgk[1][idx];
        const float kv = g_fgk[2][idx];

        float kn2 = kv * kv, jf2 = jfv * jfv, dt = kv * jgv;
#pragma unroll
        for (int off = 16; off > 0; off >>= 1) {
            kn2 += __shfl_down_sync(0xffffffffu, kn2, off);
            jf2 += __shfl_down_sync(0xffffffffu, jf2, off);
            dt  += __shfl_down_sync(0xffffffffu, dt,  off);
        }
        __shared__ float s_kn2[8], s_jf2[8], s_dt[8], s_scale;
        const int warp = i >> 5, lane = i & 31;
        if (lane == 0) { s_kn2[warp] = kn2; s_jf2[warp] = jf2; s_dt[warp] = dt; }
        __syncthreads();
        if (i == 0) {
            float tkn2 = 0.f, tjf2 = 0.f, tdt = 0.f;
#pragma unroll
            for (int ww = 0; ww < 8; ww++) {
                tkn2 += s_kn2[ww]; tjf2 += s_jf2[ww]; tdt += s_dt[ww];
            }
            const float kn   = sqrtf(tkn2);
            const float kn9  = tkn2 * tkn2 * tkn2 * tkn2 * kn;
            const float kn10 = kn9 * kn;
            const float c1 = sqrtf(tjf2) - ALPHA * kn9;
            const float c2 = tdt - BETA * kn10;
            s_scale = ((c1 > EPSC) || (c2 < -EPSC)) ? 0.5f : 1.0f;
        }
        __syncthreads();
        out[idx] = s_scale * (fv + gv);
    }
}

// inputs: 0:t 1:x 2:Wf1 3:bf1 4:Wf2 5:bf2 6:Wg1 7:bg1 8:Wg2 9:bg2 10:Wk1 11:bk1 12:Wk2 13:bk2
extern "C" void kernel_launch(void* const* d_in, const int* in_sizes, int n_in,
                              void* d_out, int out_size)
{
    const float* x   = (const float*)d_in[1];
    const float* Wf1 = (const float*)d_in[2];
    const float* bf1 = (const float*)d_in[3];
    const float* Wf2 = (const float*)d_in[4];
    const float* bf2 = (const float*)d_in[5];
    const float* Wg1 = (const float*)d_in[6];
    const float* bg1 = (const float*)d_in[7];
    const float* Wg2 = (const float*)d_in[8];
    const float* bg2 = (const float*)d_in[9];
    const float* Wk1 = (const float*)d_in[10];
    const float* bk1 = (const float*)d_in[11];
    const float* Wk2 = (const float*)d_in[12];
    const float* bk2 = (const float*)d_in[13];
    float* out = (float*)d_out;

    cudaFuncSetAttribute(fused_mma_kernel,
                         cudaFuncAttributeMaxDynamicSharedMemorySize, SMEM_TOTAL);

    int dev = 0, sms = 148;
    cudaGetDevice(&dev);
    cudaDeviceGetAttribute(&sms, cudaDevAttrMultiProcessorCount, dev);
    int occ = 1;
    cudaOccupancyMaxActiveBlocksPerMultiprocessor(&occ, fused_mma_kernel, 256, SMEM_TOTAL);
    if (occ < 1) occ = 1;
    if (occ > 2) occ = 2;
    const int grid = sms * occ;    // all co-resident -> grid barrier safe

    fused_mma_kernel<<<grid, 256, SMEM_TOTAL>>>(x, Wf1, bf1, Wf2, bf2, Wg1, bg1,
                                                Wg2, bg2, Wk1, bk1, Wk2, bk2, out);
}

// round 9
// speedup vs baseline: 2.5668x; 1.4666x over previous
#include <cuda_runtime.h>
#include <cuda_bf16.h>
#include <math.h>
#include <stdint.h>

#define BSZ  128
#define NDIM 256
#define HDIM 1024
#define ALPHA 60.0f
#define BETA  20.0f
#define EPSC  1e-8f

typedef unsigned int uint;

// ---------------- scratch (allocation-free __device__ globals) ----------------
__device__ __align__(16) __nv_bfloat16 g_xh[BSZ * NDIM],      g_xl[BSZ * NDIM];
__device__ __align__(16) __nv_bfloat16 g_W1h[3][HDIM * NDIM], g_W1l[3][HDIM * NDIM];
__device__ __align__(16) __nv_bfloat16 g_W2h[3][NDIM * HDIM], g_W2l[3][NDIM * HDIM];
__device__ __align__(16) __nv_bfloat16 g_Hh[3][BSZ * HDIM],   g_Hl[3][BSZ * HDIM];
__device__ __align__(16) float         g_fgk[3][BSZ * NDIM];
__device__ __align__(16) float         g_P2p[3][8][BSZ * NDIM];
__device__ float g_F1p[32], g_F2p[32];
__device__ int   g_bad[BSZ];

// fallback-only scratch
__device__ __align__(16) __nv_bfloat16 g_K2Th[HDIM * NDIM],  g_K2Tl[HDIM * NDIM];
__device__ __align__(16) __nv_bfloat16 g_K1Th[NDIM * HDIM],  g_K1Tl[NDIM * HDIM];
__device__ __align__(16) float         g_D[BSZ * HDIM];
__device__ __align__(16) __nv_bfloat16 g_fgh[2][BSZ * NDIM], g_fgl[2][BSZ * NDIM];
__device__ __align__(16) __nv_bfloat16 g_dvh[2][BSZ * HDIM], g_dvl[2][BSZ * HDIM];
__device__ __align__(16) float         g_P3p[2][2][BSZ * HDIM];
__device__ __align__(16) float         g_P4p[2][8][BSZ * NDIM];

// ---------------- grid barrier ----------------
__device__ int g_cnt = 0, g_sense = 0;
__device__ __forceinline__ void gbar()
{
    __threadfence();
    __syncthreads();
    if (threadIdx.x == 0) {
        int s = *(volatile int*)&g_sense;
        int old = atomicAdd(&g_cnt, 1);
        if (old == (int)gridDim.x - 1) {
            atomicExch(&g_cnt, 0);
            __threadfence();
            atomicExch(&g_sense, 1 - s);
        } else {
            while (*(volatile int*)&g_sense == s) __nanosleep(64);
        }
        __threadfence();
    }
    __syncthreads();
}

// ---------------- helpers ----------------
__device__ __forceinline__ uint smem_u32(const void* p)
{
    uint a;
    asm("{ .reg .u64 t; cvta.to.shared.u64 t, %1; cvt.u32.u64 %0, t; }"
        : "=r"(a) : "l"(p));
    return a;
}
__device__ __forceinline__ void split_bf16(float v, __nv_bfloat16& h, __nv_bfloat16& l)
{
    h = __float2bfloat16(v);
    l = __float2bfloat16(v - __bfloat162float(h));
}
__device__ __forceinline__ void st_bf2(__nv_bfloat16* p, __nv_bfloat16 a, __nv_bfloat16 b)
{
    __nv_bfloat162 t; t.x = a; t.y = b;
    *reinterpret_cast<__nv_bfloat162*>(p) = t;
}

#define CP16(dst, src) \
    asm volatile("cp.async.cg.shared.global [%0], [%1], 16;" :: "r"(dst), "l"(src))
#define CP_COMMIT() asm volatile("cp.async.commit_group;" ::: "memory")
#define CP_WAIT(n)  asm volatile("cp.async.wait_group %0;" :: "n"(n) : "memory")

#define LDM4(r, addr) \
    asm volatile("ldmatrix.sync.aligned.m8n8.x4.shared.b16 {%0,%1,%2,%3}, [%4];" \
        : "=r"((r)[0]), "=r"((r)[1]), "=r"((r)[2]), "=r"((r)[3]) : "r"(addr))

#define MMA16816(c, a, b0, b1) \
    asm volatile("mma.sync.aligned.m16n8k16.row.col.f32.bf16.bf16.f32 " \
        "{%0,%1,%2,%3}, {%4,%5,%6,%7}, {%8,%9}, {%0,%1,%2,%3};" \
        : "+f"((c)[0]), "+f"((c)[1]), "+f"((c)[2]), "+f"((c)[3]) \
        : "r"((a)[0]), "r"((a)[1]), "r"((a)[2]), "r"((a)[3]), "r"(b0), "r"(b1))

// ---------------- smem buffer layout ----------------
#define BUF_AL 16384
#define BUF_BH 32768
#define BUF_BL 40960
#define BUF_SZ 49152
#define SMEM_TOTAL (2 * BUF_SZ)

struct Job {
    const __nv_bfloat16 *Ah, *Al, *Bh, *Bl;
    int lda, ldb, k0, nch, mode, ldo, ncol0;
    float* Of;                     // mode 0
    __nv_bfloat16 *Oh, *Ol;       // mode 1
    const float* bias;             // mode 1
};

__device__ __forceinline__ void fill_chunk(uint buf, const Job& j, int kc)
{
    const int tid = threadIdx.x;
#pragma unroll
    for (int i = 0; i < 4; i++) {
        const int idx = tid + i * 256;
        const int row = idx >> 3, u = idx & 7;
        const uint sw = (uint)row * 128 + (uint)((u ^ (row & 7)) * 16);
        const size_t go = (size_t)row * j.lda + kc + u * 8;
        CP16(buf + sw,          j.Ah + go);
        CP16(buf + BUF_AL + sw, j.Al + go);
    }
#pragma unroll
    for (int i = 0; i < 2; i++) {
        const int idx = tid + i * 256;
        const int row = idx >> 3, u = idx & 7;
        const uint sw = (uint)row * 128 + (uint)((u ^ (row & 7)) * 16);
        const size_t go = (size_t)row * j.ldb + kc + u * 8;
        CP16(buf + BUF_BH + sw, j.Bh + go);
        CP16(buf + BUF_BL + sw, j.Bl + go);
    }
    CP_COMMIT();
}

__device__ __forceinline__ void compute_chunk(uint buf, float acc[2][4][4])
{
    const int lane = threadIdx.x & 31;
    const int w = threadIdx.x >> 5;
    const int m0w = (w & 3) * 32;
    const int n0w = (w >> 2) * 32;
    const int arow_l = lane & 15;
    const int au_l   = lane >> 4;
    const int brow_l = (lane & 7) + ((lane >> 4) & 1) * 8;
    const int bu_l   = (lane >> 3) & 1;

#pragma unroll
    for (int ks = 0; ks < 4; ks++) {
        uint ah[2][4], al[2][4], bh[2][4], bl[2][4];
#pragma unroll
        for (int mi = 0; mi < 2; mi++) {
            const int r = m0w + mi * 16 + arow_l;
            const int u = ks * 2 + au_l;
            const uint ad = buf + (uint)r * 128 + (uint)((u ^ (r & 7)) * 16);
            LDM4(ah[mi], ad);
            LDM4(al[mi], ad + BUF_AL);
        }
#pragma unroll
        for (int njp = 0; njp < 2; njp++) {
            const int r = n0w + njp * 16 + brow_l;
            const int u = ks * 2 + bu_l;
            const uint bd = buf + BUF_BH + (uint)r * 128 + (uint)((u ^ (r & 7)) * 16);
            LDM4(bh[njp], bd);
            LDM4(bl[njp], bd + (BUF_BL - BUF_BH));
        }
#pragma unroll
        for (int mi = 0; mi < 2; mi++)
#pragma unroll
            for (int njp = 0; njp < 2; njp++)
#pragma unroll
                for (int h = 0; h < 2; h++) {
                    float* c = acc[mi][njp * 2 + h];
                    MMA16816(c, ah[mi], bh[njp][2 * h], bh[njp][2 * h + 1]);
                    MMA16816(c, ah[mi], bl[njp][2 * h], bl[njp][2 * h + 1]);
                    MMA16816(c, al[mi], bh[njp][2 * h], bh[njp][2 * h + 1]);
                }
    }
}

__device__ __forceinline__ void store_tile(const Job& j, const float acc[2][4][4])
{
    const int lane = threadIdx.x & 31;
    const int w = threadIdx.x >> 5;
    const int g = lane >> 2, t = lane & 3;
    const int m0w = (w & 3) * 32, n0w = (w >> 2) * 32;
#pragma unroll
    for (int mi = 0; mi < 2; mi++)
#pragma unroll
        for (int nj = 0; nj < 4; nj++) {
            const int r = m0w + mi * 16 + g, c = n0w + nj * 8 + t * 2;
            if (j.mode == 0) {
                *reinterpret_cast<float2*>(&j.Of[(size_t)r * j.ldo + c]) =
                    make_float2(acc[mi][nj][0], acc[mi][nj][1]);
                *reinterpret_cast<float2*>(&j.Of[(size_t)(r + 8) * j.ldo + c]) =
                    make_float2(acc[mi][nj][2], acc[mi][nj][3]);
            } else {
                const int col = j.ncol0 + c;
                float h0 = tanhf(acc[mi][nj][0] + j.bias[col]);
                float h1 = tanhf(acc[mi][nj][1] + j.bias[col + 1]);
                __nv_bfloat16 p0, q0, p1, q1;
                split_bf16(h0, p0, q0); split_bf16(h1, p1, q1);
                st_bf2(&j.Oh[(size_t)r * j.ldo + col], p0, p1);
                st_bf2(&j.Ol[(size_t)r * j.ldo + col], q0, q1);
                float h2 = tanhf(acc[mi][nj][2] + j.bias[col]);
                float h3 = tanhf(acc[mi][nj][3] + j.bias[col + 1]);
                split_bf16(h2, p0, q0); split_bf16(h3, p1, q1);
                st_bf2(&j.Oh[(size_t)(r + 8) * j.ldo + col], p0, p1);
                st_bf2(&j.Ol[(size_t)(r + 8) * j.ldo + col], q0, q1);
            }
        }
}

template <class DEC>
__device__ void gemm_phase(uint sb, int U, const DEC& dec)
{
    const uint buf0 = sb, buf1 = sb + BUF_SZ;
    for (int u = blockIdx.x; u < U; u += gridDim.x) {
        Job j; dec(u, j);
        fill_chunk(buf0, j, j.k0);
        fill_chunk(buf1, j, j.k0 + 64);
        float acc[2][4][4];
#pragma unroll
        for (int a = 0; a < 2; a++)
#pragma unroll
            for (int b = 0; b < 4; b++)
#pragma unroll
                for (int q = 0; q < 4; q++) acc[a][b][q] = 0.f;

        for (int c = 0; c < j.nch; c++) {
            if (c == j.nch - 1) { CP_WAIT(0); } else { CP_WAIT(1); }
            __syncthreads();
            compute_chunk((c & 1) ? buf1 : buf0, acc);
            __syncthreads();
            if (c + 2 < j.nch)
                fill_chunk((c & 1) ? buf1 : buf0, j, j.k0 + (c + 2) * 64);
        }
        store_tile(j, acc);
        __syncthreads();
    }
}

// ---------------- decoders ----------------
struct DecP1 {      // U=48: z3 x n16; K=256 full, tanh epilogue
    const float* b1[3];
    __device__ void operator()(int u, Job& j) const {
        const int z = u >> 4, n = u & 15;
        j.Ah = g_xh; j.Al = g_xl; j.lda = NDIM;
        j.Bh = g_W1h[z] + (size_t)n * 64 * NDIM;
        j.Bl = g_W1l[z] + (size_t)n * 64 * NDIM; j.ldb = NDIM;
        j.k0 = 0; j.nch = 4; j.mode = 1;
        j.Oh = g_Hh[z]; j.Ol = g_Hl[z]; j.ldo = HDIM; j.ncol0 = n * 64;
        j.bias = b1[z]; j.Of = nullptr;
    }
};
struct DecP2 {      // U=96: z3 x n4 x s8; K-chunk 128, partial store
    __device__ void operator()(int u, Job& j) const {
        const int z = u >> 5, r = u & 31, n = r >> 3, s = r & 7;
        j.Ah = g_Hh[z]; j.Al = g_Hl[z]; j.lda = HDIM;
        j.Bh = g_W2h[z] + (size_t)n * 64 * HDIM;
        j.Bl = g_W2l[z] + (size_t)n * 64 * HDIM; j.ldb = HDIM;
        j.k0 = s * 128; j.nch = 2; j.mode = 0;
        j.Of = g_P2p[z][s] + n * 64; j.ldo = NDIM;
        j.Oh = nullptr; j.Ol = nullptr; j.bias = nullptr; j.ncol0 = 0;
    }
};
struct DecP3 {      // fallback. U=64: z2 x n16 x s2
    __device__ void operator()(int u, Job& j) const {
        const int z = u >> 5, r = u & 31, n = r >> 1, s = r & 1;
        j.Ah = g_fgh[z]; j.Al = g_fgl[z]; j.lda = NDIM;
        j.Bh = g_K2Th + (size_t)n * 64 * NDIM;
        j.Bl = g_K2Tl + (size_t)n * 64 * NDIM; j.ldb = NDIM;
        j.k0 = s * 128; j.nch = 2; j.mode = 0;
        j.Of = g_P3p[z][s] + n * 64; j.ldo = HDIM;
        j.Oh = nullptr; j.Ol = nullptr; j.bias = nullptr; j.ncol0 = 0;
    }
};
struct DecP4 {      // fallback. U=64: z2 x n4 x s8
    __device__ void operator()(int u, Job& j) const {
        const int z = u >> 5, r = u & 31, n = r >> 3, s = r & 7;
        j.Ah = g_dvh[z]; j.Al = g_dvl[z]; j.lda = HDIM;
        j.Bh = g_K1Th + (size_t)n * 64 * HDIM;
        j.Bl = g_K1Tl + (size_t)n * 64 * HDIM; j.ldb = HDIM;
        j.k0 = s * 128; j.nch = 2; j.mode = 0;
        j.Of = g_P4p[z][s] + n * 64; j.ldo = NDIM;
        j.Oh = nullptr; j.Ol = nullptr; j.bias = nullptr; j.ncol0 = 0;
    }
};

// ---------------- misc device funcs ----------------
__device__ void cvt_arr(const float* __restrict__ s, __nv_bfloat16* h,
                        __nv_bfloat16* l, int n4, int gtid, int gsz)
{
    for (int i = gtid; i < n4; i += gsz) {
        float4 v = reinterpret_cast<const float4*>(s)[i];
        __nv_bfloat16 h0, l0, h1, l1, h2, l2, h3, l3;
        split_bf16(v.x, h0, l0); split_bf16(v.y, h1, l1);
        split_bf16(v.z, h2, l2); split_bf16(v.w, h3, l3);
        st_bf2(&h[4 * i], h0, h1); st_bf2(&h[4 * i + 2], h2, h3);
        st_bf2(&l[4 * i], l0, l1); st_bf2(&l[4 * i + 2], l2, l3);
    }
}
__device__ void fnorm_block(const float* __restrict__ W, float* slot, float* red)
{
    float s = 0.f;
    for (int i = threadIdx.x; i < 2048; i += 256) {         // 8192 floats
        float4 v = reinterpret_cast<const float4*>(W)[i];
        s += v.x * v.x + v.y * v.y + v.z * v.z + v.w * v.w;
    }
#pragma unroll
    for (int off = 16; off > 0; off >>= 1) s += __shfl_down_sync(0xffffffffu, s, off);
    const int warp = threadIdx.x >> 5, lane = threadIdx.x & 31;
    if (lane == 0) red[warp] = s;
    __syncthreads();
    if (threadIdx.x == 0) {
        float t = 0.f;
#pragma unroll
        for (int ww = 0; ww < 8; ww++) t += red[ww];
        *slot = t;
    }
    __syncthreads();
}
__device__ void trans_tile(float (*ts)[65], const float* __restrict__ src, int lds,
                           int r0, int c0, __nv_bfloat16* dh, __nv_bfloat16* dl, int ldd)
{
    const int tid = threadIdx.x;
    __syncthreads();
    for (int i = tid; i < 4096; i += 256) {
        const int r = i >> 6, c = i & 63;
        ts[r][c] = src[(size_t)(r0 + r) * lds + c0 + c];
    }
    __syncthreads();
    for (int i = tid; i < 4096; i += 256) {
        const int dr = i >> 6, dc = i & 63;
        __nv_bfloat16 h, l;
        split_bf16(ts[dc][dr], h, l);
        dh[(size_t)(c0 + dr) * ldd + r0 + dc] = h;
        dl[(size_t)(c0 + dr) * ldd + r0 + dc] = l;
    }
}

// ---------------- persistent fused kernel ----------------
__global__ __launch_bounds__(256, 2) void fused_cert_kernel(
    const float* __restrict__ x,
    const float* __restrict__ Wf1, const float* __restrict__ bf1,
    const float* __restrict__ Wf2, const float* __restrict__ bf2,
    const float* __restrict__ Wg1, const float* __restrict__ bg1,
    const float* __restrict__ Wg2, const float* __restrict__ bg2,
    const float* __restrict__ Wk1, const float* __restrict__ bk1,
    const float* __restrict__ Wk2, const float* __restrict__ bk2,
    float* __restrict__ out)
{
    extern __shared__ char smem[];
    const uint sb = smem_u32(smem);
    float* red = reinterpret_cast<float*>(smem);
    const int tid = threadIdx.x;
    const int bid = blockIdx.x;
    const int gtid = bid * 256 + tid;
    const int gsz = gridDim.x * 256;

    // ---------- Ph0: bf16 hi/lo conversions + Frobenius partials ----------
    cvt_arr(x,   g_xh,     g_xl,     BSZ * NDIM / 4,  gtid, gsz);
    cvt_arr(Wf1, g_W1h[0], g_W1l[0], HDIM * NDIM / 4, gtid, gsz);
    cvt_arr(Wg1, g_W1h[1], g_W1l[1], HDIM * NDIM / 4, gtid, gsz);
    cvt_arr(Wk1, g_W1h[2], g_W1l[2], HDIM * NDIM / 4, gtid, gsz);
    cvt_arr(Wf2, g_W2h[0], g_W2l[0], NDIM * HDIM / 4, gtid, gsz);
    cvt_arr(Wg2, g_W2h[1], g_W2l[1], NDIM * HDIM / 4, gtid, gsz);
    cvt_arr(Wk2, g_W2h[2], g_W2l[2], NDIM * HDIM / 4, gtid, gsz);
    if (bid < 32)       fnorm_block(Wk1 + bid * 8192,        &g_F1p[bid],      red);
    else if (bid < 64)  fnorm_block(Wk2 + (bid - 32) * 8192, &g_F2p[bid - 32], red);
    gbar();

    // ---------- P1: H[z] = tanh(x @ W1[z]^T + b1), fused epilogue ----------
    {
        DecP1 d; d.b1[0] = bf1; d.b1[1] = bg1; d.b1[2] = bk1;
        gemm_phase(sb, 48, d);
    }
    gbar();

    // ---------- P2: partials p2[z][s] ----------
    gemm_phase(sb, 96, DecP2{});
    gbar();

    // ---------- Ph2b: fgk, speculative out, per-row certification ----------
    if (bid < BSZ) {
        const int b = bid, i = tid;
        const int idx = b * NDIM + i;
        float fv = bf2[i], gv = bg2[i], kv = bk2[i];
#pragma unroll
        for (int s = 0; s < 8; s++) {
            fv += g_P2p[0][s][idx];
            gv += g_P2p[1][s][idx];
            kv += g_P2p[2][s][idx];
        }
        g_fgk[0][idx] = fv; g_fgk[1][idx] = gv; g_fgk[2][idx] = kv;
        out[idx] = 0.5f * (fv + gv);            // speculative (mask certified below)

        float kn2 = kv * kv, gn2 = gv * gv;
#pragma unroll
        for (int off = 16; off > 0; off >>= 1) {
            kn2 += __shfl_down_sync(0xffffffffu, kn2, off);
            gn2 += __shfl_down_sync(0xffffffffu, gn2, off);
        }
        const int warp = i >> 5, lane = i & 31;
        if (lane == 0) { red[warp] = kn2; red[8 + warp] = gn2; }
        __syncthreads();
        if (i == 0) {
            float tkn2 = 0.f, tgn2 = 0.f;
#pragma unroll
            for (int ww = 0; ww < 8; ww++) { tkn2 += red[ww]; tgn2 += red[8 + ww]; }
            float F1sq = 0.f, F2sq = 0.f;
#pragma unroll
            for (int p = 0; p < 32; p++) { F1sq += g_F1p[p]; F2sq += g_F2p[p]; }
            const float F  = sqrtf(F1sq) * sqrtf(F2sq);
            const float kn = sqrtf(tkn2), gn = sqrtf(tgn2);
            const float kn10 = tkn2 * tkn2 * tkn2 * tkn2 * tkn2;   // kn^10
            // certify  c2 = <k,JG> - BETA*kn^10 < -EPSC  via |<k,JG>| <= kn*F*gn
            const int certified = (BETA * kn10 > 2.0f * kn * F * gn + 1.0f);
            g_bad[b] = certified ? 0 : 1;
        }
        __syncthreads();
    }
    gbar();

    // ---------- decision (uniform across grid) ----------
    {
        int bad = (tid < BSZ) ? g_bad[tid] : 0;
        if (__syncthreads_or(bad) == 0) return;    // fast path done
    }

    // ================= FALLBACK (certified-impossible, but exact) =================
    // FB-A: D, fg hi/lo, weight transposes
    for (int i = gtid; i < BSZ * HDIM; i += gsz) {
        const float t = __bfloat162float(g_Hh[2][i]) + __bfloat162float(g_Hl[2][i]);
        g_D[i] = 1.0f - t * t;
    }
    for (int i = gtid; i < 2 * BSZ * NDIM; i += gsz) {
        const int z = i / (BSZ * NDIM), j = i - z * (BSZ * NDIM);
        __nv_bfloat16 h, l;
        split_bf16(g_fgk[z][j], h, l);
        g_fgh[z][j] = h; g_fgl[z][j] = l;
    }
    {
        float (*ts)[65] = reinterpret_cast<float(*)[65]>(smem);
        for (int t = bid; t < 128; t += gridDim.x) {
            if (t < 64)
                trans_tile(ts, Wk1, NDIM, (t >> 2) * 64, (t & 3) * 64, g_K1Th, g_K1Tl, HDIM);
            else {
                const int tt = t - 64;
                trans_tile(ts, Wk2, HDIM, (tt & 3) * 64, (tt >> 2) * 64, g_K2Th, g_K2Tl, NDIM);
            }
        }
    }
    gbar();
    gemm_phase(sb, 64, DecP3{});
    gbar();
    for (int i = gtid; i < 2 * BSZ * HDIM; i += gsz) {
        const int z = i / (BSZ * HDIM), j = i - z * (BSZ * HDIM);
        const float v = (g_P3p[z][0][j] + g_P3p[z][1][j]) * g_D[j];
        __nv_bfloat16 h, l;
        split_bf16(v, h, l);
        g_dvh[z][j] = h; g_dvl[z][j] = l;
    }
    gbar();
    gemm_phase(sb, 64, DecP4{});
    gbar();
    if (bid < BSZ) {
        const int b = bid, i = tid;
        const int idx = b * NDIM + i;
        float jfv = 0.f, jgv = 0.f;
#pragma unroll
        for (int s = 0; s < 8; s++) {
            jfv += g_P4p[0][s][idx];
            jgv += g_P4p[1][s][idx];
        }
        const float fv = g_fgk[0][idx];
        const float gv = g_fgk[1][idx];
        const float kv = g_fgk[2][idx];
        float kn2 = kv * kv, jf2 = jfv * jfv, dt = kv * jgv;
#pragma unroll
        for (int off = 16; off > 0; off >>= 1) {
            kn2 += __shfl_down_sync(0xffffffffu, kn2, off);
            jf2 += __shfl_down_sync(0xffffffffu, jf2, off);
            dt  += __shfl_down_sync(0xffffffffu, dt,  off);
        }
        const int warp = i >> 5, lane = i & 31;
        if (lane == 0) { red[warp] = kn2; red[8 + warp] = jf2; red[16 + warp] = dt; }
        __syncthreads();
        __shared__ float s_scale;
        if (i == 0) {
            float tkn2 = 0.f, tjf2 = 0.f, tdt = 0.f;
#pragma unroll
            for (int ww = 0; ww < 8; ww++) {
                tkn2 += red[ww]; tjf2 += red[8 + ww]; tdt += red[16 + ww];
            }
            const float kn   = sqrtf(tkn2);
            const float kn9  = tkn2 * tkn2 * tkn2 * tkn2 * kn;
            const float kn10 = kn9 * kn;
            const float c1 = sqrtf(tjf2) - ALPHA * kn9;
            const float c2 = tdt - BETA * kn10;
            s_scale = ((c1 > EPSC) || (c2 < -EPSC)) ? 0.5f : 1.0f;
        }
        __syncthreads();
        out[idx] = s_scale * (fv + gv);
    }
}

// inputs: 0:t 1:x 2:Wf1 3:bf1 4:Wf2 5:bf2 6:Wg1 7:bg1 8:Wg2 9:bg2 10:Wk1 11:bk1 12:Wk2 13:bk2
extern "C" void kernel_launch(void* const* d_in, const int* in_sizes, int n_in,
                              void* d_out, int out_size)
{
    const float* x   = (const float*)d_in[1];
    const float* Wf1 = (const float*)d_in[2];
    const float* bf1 = (const float*)d_in[3];
    const float* Wf2 = (const float*)d_in[4];
    const float* bf2 = (const float*)d_in[5];
    const float* Wg1 = (const float*)d_in[6];
    const float* bg1 = (const float*)d_in[7];
    const float* Wg2 = (const float*)d_in[8];
    const float* bg2 = (const float*)d_in[9];
    const float* Wk1 = (const float*)d_in[10];
    const float* bk1 = (const float*)d_in[11];
    const float* Wk2 = (const float*)d_in[12];
    const float* bk2 = (const float*)d_in[13];
    float* out = (float*)d_out;

    cudaFuncSetAttribute(fused_cert_kernel,
                         cudaFuncAttributeMaxDynamicSharedMemorySize, SMEM_TOTAL);

    int dev = 0, sms = 148;
    cudaGetDevice(&dev);
    cudaDeviceGetAttribute(&sms, cudaDevAttrMultiProcessorCount, dev);
    int occ = 1;
    cudaOccupancyMaxActiveBlocksPerMultiprocessor(&occ, fused_cert_kernel, 256, SMEM_TOTAL);
    if (occ < 1) occ = 1;
    if (occ > 2) occ = 2;
    const int grid = sms * occ;

    fused_cert_kernel<<<grid, 256, SMEM_TOTAL>>>(x, Wf1, bf1, Wf2, bf2, Wg1, bg1,
                                                 Wg2, bg2, Wk1, bk1, Wk2, bk2, out);
}

// round 10
// speedup vs baseline: 3.7361x; 1.4556x over previous
#include <cuda_runtime.h>
#include <cuda_bf16.h>
#include <math.h>
#include <stdint.h>

#define BSZ  128
#define NDIM 256
#define HDIM 1024
#define ALPHA 60.0f
#define BETA  20.0f
#define EPSC  1e-8f

typedef unsigned int uint;

// ---------------- scratch (allocation-free __device__ globals) ----------------
__device__ __align__(16) __nv_bfloat16 g_Hh[3][BSZ * HDIM], g_Hl[3][BSZ * HDIM];
__device__ __align__(16) float         g_fgk[3][BSZ * NDIM];
__device__ __align__(16) float         g_P2p[3][8][BSZ * NDIM];
__device__ float g_F1p[32], g_F2p[32];
__device__ int   g_bad[BSZ];

// fallback-only scratch
__device__ __align__(16) __nv_bfloat16 g_K2Th[HDIM * NDIM],  g_K2Tl[HDIM * NDIM];
__device__ __align__(16) __nv_bfloat16 g_K1Th[NDIM * HDIM],  g_K1Tl[NDIM * HDIM];
__device__ __align__(16) float         g_D[BSZ * HDIM];
__device__ __align__(16) __nv_bfloat16 g_fgh[2][BSZ * NDIM], g_fgl[2][BSZ * NDIM];
__device__ __align__(16) __nv_bfloat16 g_dvh[2][BSZ * HDIM], g_dvl[2][BSZ * HDIM];
__device__ __align__(16) float         g_P3p[2][2][BSZ * HDIM];
__device__ __align__(16) float         g_P4p[2][8][BSZ * NDIM];

// ---------------- grid barrier ----------------
__device__ int g_cnt = 0, g_sense = 0;
__device__ __forceinline__ void gbar()
{
    __threadfence();
    __syncthreads();
    if (threadIdx.x == 0) {
        int s = *(volatile int*)&g_sense;
        int old = atomicAdd(&g_cnt, 1);
        if (old == (int)gridDim.x - 1) {
            atomicExch(&g_cnt, 0);
            __threadfence();
            atomicExch(&g_sense, 1 - s);
        } else {
            while (*(volatile int*)&g_sense == s) __nanosleep(64);
        }
        __threadfence();
    }
    __syncthreads();
}

// ---------------- helpers ----------------
__device__ __forceinline__ uint smem_u32(const void* p)
{
    uint a;
    asm("{ .reg .u64 t; cvta.to.shared.u64 t, %1; cvt.u32.u64 %0, t; }"
        : "=r"(a) : "l"(p));
    return a;
}
__device__ __forceinline__ void split_bf16(float v, __nv_bfloat16& h, __nv_bfloat16& l)
{
    h = __float2bfloat16(v);
    l = __float2bfloat16(v - __bfloat162float(h));
}
__device__ __forceinline__ void st_bf2(__nv_bfloat16* p, __nv_bfloat16 a, __nv_bfloat16 b)
{
    __nv_bfloat162 t; t.x = a; t.y = b;
    *reinterpret_cast<__nv_bfloat162*>(p) = t;
}
__device__ __forceinline__ uint pack2(__nv_bfloat16 a, __nv_bfloat16 b)
{
    __nv_bfloat162 t; t.x = a; t.y = b;
    return *reinterpret_cast<uint*>(&t);
}
__device__ __forceinline__ void split4(float4 v, uint2& hu, uint2& lu)
{
    __nv_bfloat16 h0, l0, h1, l1, h2, l2, h3, l3;
    split_bf16(v.x, h0, l0); split_bf16(v.y, h1, l1);
    split_bf16(v.z, h2, l2); split_bf16(v.w, h3, l3);
    hu.x = pack2(h0, h1); hu.y = pack2(h2, h3);
    lu.x = pack2(l0, l1); lu.y = pack2(l2, l3);
}
// fast-exact tanh (verified rounds 4-5): abs err ~1e-7
__device__ __forceinline__ float frcp(float x)
{
    float r;
    asm("rcp.approx.f32 %0, %1;" : "=f"(r) : "f"(x));
    return r;
}
__device__ __forceinline__ float ftanh(float x)
{
    float ax = fabsf(x);
    float e = __expf(ax + ax);
    float t = 1.0f - 2.0f * frcp(e + 1.0f);
    return copysignf(t, x);
}

#define CP16(dst, src) \
    asm volatile("cp.async.cg.shared.global [%0], [%1], 16;" :: "r"(dst), "l"(src))
#define CP_COMMIT() asm volatile("cp.async.commit_group;" ::: "memory")
#define CP_WAIT(n)  asm volatile("cp.async.wait_group %0;" :: "n"(n) : "memory")

#define LDM4(r, addr) \
    asm volatile("ldmatrix.sync.aligned.m8n8.x4.shared.b16 {%0,%1,%2,%3}, [%4];" \
        : "=r"((r)[0]), "=r"((r)[1]), "=r"((r)[2]), "=r"((r)[3]) : "r"(addr))

#define MMA16816(c, a, b0, b1) \
    asm volatile("mma.sync.aligned.m16n8k16.row.col.f32.bf16.bf16.f32 " \
        "{%0,%1,%2,%3}, {%4,%5,%6,%7}, {%8,%9}, {%0,%1,%2,%3};" \
        : "+f"((c)[0]), "+f"((c)[1]), "+f"((c)[2]), "+f"((c)[3]) \
        : "r"((a)[0]), "r"((a)[1]), "r"((a)[2]), "r"((a)[3]), "r"(b0), "r"(b1))

// ---------------- smem layout ----------------
#define BUF_AL 16384
#define BUF_BH 32768
#define BUF_BL 40960
#define BUF_SZ 49152
#define SMEM_TOTAL (2 * BUF_SZ)
// P1 buffer sublayout (n=32 B tile): Ah 16K | Al 16K | Bh 4K | Bl 4K
#define P1_AL 16384
#define P1_BH 32768
#define P1_BL 36864

// ============================================================
// compute64: 128x64 tile, one K=64 chunk (round-9 verified layout)
// 8 warps = 4m x 2n, warp tile 32x32
// ============================================================
__device__ __forceinline__ void compute64(uint buf, float acc[2][4][4])
{
    const int lane = threadIdx.x & 31;
    const int w = threadIdx.x >> 5;
    const int m0w = (w & 3) * 32;
    const int n0w = (w >> 2) * 32;
    const int arow_l = lane & 15;
    const int au_l   = lane >> 4;
    const int brow_l = (lane & 7) + ((lane >> 4) & 1) * 8;
    const int bu_l   = (lane >> 3) & 1;

#pragma unroll
    for (int ks = 0; ks < 4; ks++) {
        uint ah[2][4], al[2][4], bh[2][4], bl[2][4];
#pragma unroll
        for (int mi = 0; mi < 2; mi++) {
            const int r = m0w + mi * 16 + arow_l;
            const int u = ks * 2 + au_l;
            const uint ad = buf + (uint)r * 128 + (uint)((u ^ (r & 7)) * 16);
            LDM4(ah[mi], ad);
            LDM4(al[mi], ad + BUF_AL);
        }
#pragma unroll
        for (int njp = 0; njp < 2; njp++) {
            const int r = n0w + njp * 16 + brow_l;
            const int u = ks * 2 + bu_l;
            const uint bd = buf + BUF_BH + (uint)r * 128 + (uint)((u ^ (r & 7)) * 16);
            LDM4(bh[njp], bd);
            LDM4(bl[njp], bd + (BUF_BL - BUF_BH));
        }
#pragma unroll
        for (int mi = 0; mi < 2; mi++)
#pragma unroll
            for (int njp = 0; njp < 2; njp++)
#pragma unroll
                for (int h = 0; h < 2; h++) {
                    float* c = acc[mi][njp * 2 + h];
                    MMA16816(c, ah[mi], bh[njp][2 * h], bh[njp][2 * h + 1]);
                    MMA16816(c, ah[mi], bl[njp][2 * h], bl[njp][2 * h + 1]);
                    MMA16816(c, al[mi], bh[njp][2 * h], bh[njp][2 * h + 1]);
                }
    }
}

// ============================================================
// compute32: 128x32 tile, one K=64 chunk. 8 warps = 8m x 1n, warp tile 16x32.
// ============================================================
__device__ __forceinline__ void compute32(uint buf, float acc[4][4])
{
    const int lane = threadIdx.x & 31;
    const int w = threadIdx.x >> 5;
    const int arow = w * 16 + (lane & 15);
    const int au_l = lane >> 4;
    const int brow_l = (lane & 7) + ((lane >> 4) & 1) * 8;
    const int bu_l   = (lane >> 3) & 1;

#pragma unroll
    for (int ks = 0; ks < 4; ks++) {
        uint ah[4], al[4], bh[2][4], bl[2][4];
        {
            const int u = ks * 2 + au_l;
            const uint ad = buf + (uint)arow * 128 + (uint)((u ^ (arow & 7)) * 16);
            LDM4(ah, ad);
            LDM4(al, ad + P1_AL);
        }
#pragma unroll
        for (int njp = 0; njp < 2; njp++) {
            const int r = njp * 16 + brow_l;
            const int u = ks * 2 + bu_l;
            const uint bd = buf + P1_BH + (uint)r * 128 + (uint)((u ^ (r & 7)) * 16);
            LDM4(bh[njp], bd);
            LDM4(bl[njp], bd + (P1_BL - P1_BH));
        }
#pragma unroll
        for (int njp = 0; njp < 2; njp++)
#pragma unroll
            for (int h = 0; h < 2; h++) {
                float* c = acc[njp * 2 + h];
                MMA16816(c, ah, bh[njp][2 * h], bh[njp][2 * h + 1]);
                MMA16816(c, ah, bl[njp][2 * h], bl[njp][2 * h + 1]);
                MMA16816(c, al, bh[njp][2 * h], bh[njp][2 * h + 1]);
            }
    }
}

// ============================================================
// P1 unit: H[z][:, n*32..+32] = tanh(x @ W1[z]^T + b1), K=256 (4 chunks)
// x, W1 read as fp32 and split in-register (no pre-conversion pass).
// ============================================================
__device__ void p1_unit(char* smem, uint sb, int z, int n,
                        const float* __restrict__ x,
                        const float* __restrict__ W1full,
                        const float* __restrict__ b1)
{
    const int tid = threadIdx.x;
    const int lane = tid & 31, w = tid >> 5;
    const float* W = W1full + (size_t)n * 32 * NDIM;   // 32 rows of W1
    char* cbuf[2] = {smem, smem + BUF_SZ};
    const uint bufs[2] = {sb, sb + BUF_SZ};

    const int ar  = tid >> 4;          // A row base (i*16 + ar)
    const int ak4 = (tid & 15) * 4;    // A k float offset
    const int au  = (tid & 15) >> 1;   // 16B unit
    const int ah8 = (tid & 1) * 8;

    float4 ax[8]; float4 bw[2];

    auto ldgs = [&](int kc) {
#pragma unroll
        for (int i = 0; i < 8; i++)
            ax[i] = *reinterpret_cast<const float4*>(
                &x[(size_t)(i * 16 + ar) * NDIM + kc + ak4]);
#pragma unroll
        for (int i = 0; i < 2; i++) {
            const int idx = i * 256 + tid;
            bw[i] = *reinterpret_cast<const float4*>(
                &W[(size_t)(idx >> 4) * NDIM + kc + (idx & 15) * 4]);
        }
    };
    auto sts = [&](char* b) {
#pragma unroll
        for (int i = 0; i < 8; i++) {
            const int row = i * 16 + ar;
            const uint off = (uint)row * 128 + (uint)((au ^ (row & 7)) * 16) + ah8;
            uint2 hu, lu; split4(ax[i], hu, lu);
            *reinterpret_cast<uint2*>(b + off)         = hu;
            *reinterpret_cast<uint2*>(b + P1_AL + off) = lu;
        }
#pragma unroll
        for (int i = 0; i < 2; i++) {
            const int idx = i * 256 + tid;
            const int row = idx >> 4;
            const int u = (idx & 15) >> 1, h8 = (idx & 1) * 8;
            const uint off = (uint)row * 128 + (uint)((u ^ (row & 7)) * 16) + h8;
            uint2 hu, lu; split4(bw[i], hu, lu);
            *reinterpret_cast<uint2*>(b + P1_BH + off) = hu;
            *reinterpret_cast<uint2*>(b + P1_BL + off) = lu;
        }
    };

    float acc[4][4];
#pragma unroll
    for (int a = 0; a < 4; a++)
#pragma unroll
        for (int q = 0; q < 4; q++) acc[a][q] = 0.f;

    ldgs(0);
    sts(cbuf[0]);
    ldgs(64);
    __syncthreads();
#pragma unroll
    for (int c = 0; c < 4; c++) {
        compute32(bufs[c & 1], acc);
        if (c < 3) {
            sts(cbuf[(c + 1) & 1]);
            if (c < 2) ldgs((c + 2) * 64);
        }
        __syncthreads();
    }

    // epilogue: tanh + hi/lo split into g_Hh/g_Hl
    const int g = lane >> 2, t4 = lane & 3;
    const int row = w * 16 + g;
#pragma unroll
    for (int nj = 0; nj < 4; nj++) {
        const int col = n * 32 + nj * 8 + t4 * 2;
        float h0 = ftanh(acc[nj][0] + b1[col]);
        float h1 = ftanh(acc[nj][1] + b1[col + 1]);
        __nv_bfloat16 p0, q0, p1, q1;
        split_bf16(h0, p0, q0); split_bf16(h1, p1, q1);
        st_bf2(&g_Hh[z][(size_t)row * HDIM + col], p0, p1);
        st_bf2(&g_Hl[z][(size_t)row * HDIM + col], q0, q1);
        float h2 = ftanh(acc[nj][2] + b1[col]);
        float h3 = ftanh(acc[nj][3] + b1[col + 1]);
        split_bf16(h2, p0, q0); split_bf16(h3, p1, q1);
        st_bf2(&g_Hh[z][(size_t)(row + 8) * HDIM + col], p0, p1);
        st_bf2(&g_Hl[z][(size_t)(row + 8) * HDIM + col], q0, q1);
    }
}

// ============================================================
// P2 unit: g_P2p[z][s][:, n*64..] = H[z][:, s*128..] @ W2[z][n*64.., s*128..]^T
// A from bf16 H (LDG-staged), B from fp32 W2 (split in-register).
// ============================================================
__device__ void p2_unit(char* smem, uint sb, int z, int n, int s,
                        const float* __restrict__ W2full)
{
    const int tid = threadIdx.x;
    const int lane = tid & 31, w = tid >> 5;
    const int k0 = s * 128;
    const __nv_bfloat16* Ah = g_Hh[z];
    const __nv_bfloat16* Al = g_Hl[z];
    const float* W = W2full + (size_t)n * 64 * HDIM;
    char* cbuf[2] = {smem, smem + BUF_SZ};
    const uint bufs[2] = {sb, sb + BUF_SZ};

    uint4 axh[4], axl[4]; float4 bw[4];

    auto ldgs = [&](int kc) {
#pragma unroll
        for (int i = 0; i < 4; i++) {
            const int idx = i * 256 + tid;
            const int row = idx >> 3, u = idx & 7;
            axh[i] = *reinterpret_cast<const uint4*>(&Ah[(size_t)row * HDIM + kc + u * 8]);
            axl[i] = *reinterpret_cast<const uint4*>(&Al[(size_t)row * HDIM + kc + u * 8]);
        }
#pragma unroll
        for (int i = 0; i < 4; i++) {
            const int idx = i * 256 + tid;
            bw[i] = *reinterpret_cast<const float4*>(
                &W[(size_t)(idx >> 4) * HDIM + kc + (idx & 15) * 4]);
        }
    };
    auto sts = [&](char* b) {
#pragma unroll
        for (int i = 0; i < 4; i++) {
            const int idx = i * 256 + tid;
            const int row = idx >> 3, u = idx & 7;
            const uint off = (uint)row * 128 + (uint)((u ^ (row & 7)) * 16);
            *reinterpret_cast<uint4*>(b + off)          = axh[i];
            *reinterpret_cast<uint4*>(b + BUF_AL + off) = axl[i];
        }
#pragma unroll
        for (int i = 0; i < 4; i++) {
            const int idx = i * 256 + tid;
            const int row = idx >> 4;
            const int u = (idx & 15) >> 1, h8 = (idx & 1) * 8;
            const uint off = (uint)row * 128 + (uint)((u ^ (row & 7)) * 16) + h8;
            uint2 hu, lu; split4(bw[i], hu, lu);
            *reinterpret_cast<uint2*>(b + BUF_BH + off) = hu;
            *reinterpret_cast<uint2*>(b + BUF_BL + off) = lu;
        }
    };

    float acc[2][4][4];
#pragma unroll
    for (int a = 0; a < 2; a++)
#pragma unroll
        for (int bq = 0; bq < 4; bq++)
#pragma unroll
            for (int q = 0; q < 4; q++) acc[a][bq][q] = 0.f;

    ldgs(k0);
    sts(cbuf[0]);
    ldgs(k0 + 64);
    __syncthreads();
    compute64(bufs[0], acc);
    sts(cbuf[1]);
    __syncthreads();
    compute64(bufs[1], acc);

    // store fp32 partial
    float* O = g_P2p[z][s] + n * 64;
    const int g = lane >> 2, t4 = lane & 3;
    const int m0w = (w & 3) * 32, n0w = (w >> 2) * 32;
#pragma unroll
    for (int mi = 0; mi < 2; mi++)
#pragma unroll
        for (int nj = 0; nj < 4; nj++) {
            const int r = m0w + mi * 16 + g, c = n0w + nj * 8 + t4 * 2;
            *reinterpret_cast<float2*>(&O[(size_t)r * NDIM + c]) =
                make_float2(acc[mi][nj][0], acc[mi][nj][1]);
            *reinterpret_cast<float2*>(&O[(size_t)(r + 8) * NDIM + c]) =
                make_float2(acc[mi][nj][2], acc[mi][nj][3]);
        }
}

// ================= fallback machinery (round-9 verified, rarely used) =========
struct Job {
    const __nv_bfloat16 *Ah, *Al, *Bh, *Bl;
    int lda, ldb, k0, nch, ldo;
    float* Of;
};
__device__ __forceinline__ void fill_chunk(uint buf, const Job& j, int kc)
{
    const int tid = threadIdx.x;
#pragma unroll
    for (int i = 0; i < 4; i++) {
        const int idx = tid + i * 256;
        const int row = idx >> 3, u = idx & 7;
        const uint sw = (uint)row * 128 + (uint)((u ^ (row & 7)) * 16);
        const size_t go = (size_t)row * j.lda + kc + u * 8;
        CP16(buf + sw,          j.Ah + go);
        CP16(buf + BUF_AL + sw, j.Al + go);
    }
#pragma unroll
    for (int i = 0; i < 2; i++) {
        const int idx = tid + i * 256;
        const int row = idx >> 3, u = idx & 7;
        const uint sw = (uint)row * 128 + (uint)((u ^ (row & 7)) * 16);
        const size_t go = (size_t)row * j.ldb + kc + u * 8;
        CP16(buf + BUF_BH + sw, j.Bh + go);
        CP16(buf + BUF_BL + sw, j.Bl + go);
    }
    CP_COMMIT();
}
__device__ __forceinline__ void store_tile(const Job& j, const float acc[2][4][4])
{
    const int lane = threadIdx.x & 31;
    const int w = threadIdx.x >> 5;
    const int g = lane >> 2, t = lane & 3;
    const int m0w = (w & 3) * 32, n0w = (w >> 2) * 32;
#pragma unroll
    for (int mi = 0; mi < 2; mi++)
#pragma unroll
        for (int nj = 0; nj < 4; nj++) {
            const int r = m0w + mi * 16 + g, c = n0w + nj * 8 + t * 2;
            *reinterpret_cast<float2*>(&j.Of[(size_t)r * j.ldo + c]) =
                make_float2(acc[mi][nj][0], acc[mi][nj][1]);
            *reinterpret_cast<float2*>(&j.Of[(size_t)(r + 8) * j.ldo + c]) =
                make_float2(acc[mi][nj][2], acc[mi][nj][3]);
        }
}
template <class DEC>
__device__ void gemm_phase(uint sb, int U, const DEC& dec)
{
    const uint buf0 = sb, buf1 = sb + BUF_SZ;
    for (int u = blockIdx.x; u < U; u += gridDim.x) {
        Job j; dec(u, j);
        fill_chunk(buf0, j, j.k0);
        fill_chunk(buf1, j, j.k0 + 64);
        float acc[2][4][4];
#pragma unroll
        for (int a = 0; a < 2; a++)
#pragma unroll
            for (int b = 0; b < 4; b++)
#pragma unroll
                for (int q = 0; q < 4; q++) acc[a][b][q] = 0.f;
        for (int c = 0; c < j.nch; c++) {
            if (c == j.nch - 1) { CP_WAIT(0); } else { CP_WAIT(1); }
            __syncthreads();
            compute64((c & 1) ? buf1 : buf0, acc);
            __syncthreads();
            if (c + 2 < j.nch)
                fill_chunk((c & 1) ? buf1 : buf0, j, j.k0 + (c + 2) * 64);
        }
        store_tile(j, acc);
        __syncthreads();
    }
}
struct DecP3 {
    __device__ void operator()(int u, Job& j) const {
        const int z = u >> 5, r = u & 31, n = r >> 1, s = r & 1;
        j.Ah = g_fgh[z]; j.Al = g_fgl[z]; j.lda = NDIM;
        j.Bh = g_K2Th + (size_t)n * 64 * NDIM;
        j.Bl = g_K2Tl + (size_t)n * 64 * NDIM; j.ldb = NDIM;
        j.k0 = s * 128; j.nch = 2;
        j.Of = g_P3p[z][s] + n * 64; j.ldo = HDIM;
    }
};
struct DecP4 {
    __device__ void operator()(int u, Job& j) const {
        const int z = u >> 5, r = u & 31, n = r >> 3, s = r & 7;
        j.Ah = g_dvh[z]; j.Al = g_dvl[z]; j.lda = HDIM;
        j.Bh = g_K1Th + (size_t)n * 64 * HDIM;
        j.Bl = g_K1Tl + (size_t)n * 64 * HDIM; j.ldb = HDIM;
        j.k0 = s * 128; j.nch = 2;
        j.Of = g_P4p[z][s] + n * 64; j.ldo = NDIM;
    }
};
__device__ void fnorm_block(const float* __restrict__ W, float* slot, float* red)
{
    float s = 0.f;
    for (int i = threadIdx.x; i < 2048; i += 256) {
        float4 v = reinterpret_cast<const float4*>(W)[i];
        s += v.x * v.x + v.y * v.y + v.z * v.z + v.w * v.w;
    }
#pragma unroll
    for (int off = 16; off > 0; off >>= 1) s += __shfl_down_sync(0xffffffffu, s, off);
    const int warp = threadIdx.x >> 5, lane = threadIdx.x & 31;
    if (lane == 0) red[warp] = s;
    __syncthreads();
    if (threadIdx.x == 0) {
        float t = 0.f;
#pragma unroll
        for (int ww = 0; ww < 8; ww++) t += red[ww];
        *slot = t;
    }
    __syncthreads();
}
__device__ void trans_tile(float (*ts)[65], const float* __restrict__ src, int lds,
                           int r0, int c0, __nv_bfloat16* dh, __nv_bfloat16* dl, int ldd)
{
    const int tid = threadIdx.x;
    __syncthreads();
    for (int i = tid; i < 4096; i += 256) {
        const int r = i >> 6, c = i & 63;
        ts[r][c] = src[(size_t)(r0 + r) * lds + c0 + c];
    }
    __syncthreads();
    for (int i = tid; i < 4096; i += 256) {
        const int dr = i >> 6, dc = i & 63;
        __nv_bfloat16 h, l;
        split_bf16(ts[dc][dr], h, l);
        dh[(size_t)(c0 + dr) * ldd + r0 + dc] = h;
        dl[(size_t)(c0 + dr) * ldd + r0 + dc] = l;
    }
}

// ---------------- persistent fused kernel ----------------
__global__ __launch_bounds__(256, 2) void fused_v2_kernel(
    const float* __restrict__ x,
    const float* __restrict__ Wf1, const float* __restrict__ bf1,
    const float* __restrict__ Wf2, const float* __restrict__ bf2,
    const float* __restrict__ Wg1, const float* __restrict__ bg1,
    const float* __restrict__ Wg2, const float* __restrict__ bg2,
    const float* __restrict__ Wk1, const float* __restrict__ bk1,
    const float* __restrict__ Wk2, const float* __restrict__ bk2,
    float* __restrict__ out)
{
    extern __shared__ char smem[];
    const uint sb = smem_u32(smem);
    float* red = reinterpret_cast<float*>(smem);
    const int tid = threadIdx.x;
    const int bid = blockIdx.x;
    const int gtid = bid * 256 + tid;
    const int gsz = gridDim.x * 256;

    // ---------- Phase A: P1 (blocks 0..95)  ||  fnorm (blocks 96..) ----------
    if (bid < 96) {
        const int z = bid >> 5, n = bid & 31;
        const float* W1 = (z == 0) ? Wf1 : (z == 1) ? Wg1 : Wk1;
        const float* b1 = (z == 0) ? bf1 : (z == 1) ? bg1 : bk1;
        p1_unit(smem, sb, z, n, x, W1, b1);
    } else {
        const int span = gridDim.x - 96;
        for (int jb = bid - 96; jb < 64; jb += span) {
            if (jb < 32) fnorm_block(Wk1 + (size_t)jb * 8192, &g_F1p[jb], red);
            else         fnorm_block(Wk2 + (size_t)(jb - 32) * 8192, &g_F2p[jb - 32], red);
        }
    }
    gbar();

    // ---------- Phase B: P2 (96 units) ----------
    if (bid < 96) {
        const int z = bid >> 5, r = bid & 31, n = r >> 3, s = r & 7;
        const float* W2 = (z == 0) ? Wf2 : (z == 1) ? Wg2 : Wk2;
        p2_unit(smem, sb, z, n, s, W2);
    }
    gbar();

    // ---------- Phase C: fgk, speculative out, per-row certification ----------
    if (bid < BSZ) {
        const int b = bid, i = tid;
        const int idx = b * NDIM + i;
        float fv = bf2[i], gv = bg2[i], kv = bk2[i];
#pragma unroll
        for (int s = 0; s < 8; s++) {
            fv += g_P2p[0][s][idx];
            gv += g_P2p[1][s][idx];
            kv += g_P2p[2][s][idx];
        }
        g_fgk[0][idx] = fv; g_fgk[1][idx] = gv; g_fgk[2][idx] = kv;
        out[idx] = 0.5f * (fv + gv);          // speculative (certified below)

        float kn2 = kv * kv, gn2 = gv * gv;
#pragma unroll
        for (int off = 16; off > 0; off >>= 1) {
            kn2 += __shfl_down_sync(0xffffffffu, kn2, off);
            gn2 += __shfl_down_sync(0xffffffffu, gn2, off);
        }
        const int warp = i >> 5, lane = i & 31;
        if (lane == 0) { red[warp] = kn2; red[8 + warp] = gn2; }
        __syncthreads();
        if (i == 0) {
            float tkn2 = 0.f, tgn2 = 0.f;
#pragma unroll
            for (int ww = 0; ww < 8; ww++) { tkn2 += red[ww]; tgn2 += red[8 + ww]; }
            float F1sq = 0.f, F2sq = 0.f;
#pragma unroll
            for (int p = 0; p < 32; p++) { F1sq += g_F1p[p]; F2sq += g_F2p[p]; }
            const float F  = sqrtf(F1sq) * sqrtf(F2sq);
            const float kn = sqrtf(tkn2), gn = sqrtf(tgn2);
            const float kn10 = tkn2 * tkn2 * tkn2 * tkn2 * tkn2;
            const int certified = (BETA * kn10 > 2.0f * kn * F * gn + 1.0f);
            g_bad[b] = certified ? 0 : 1;
        }
        __syncthreads();
    }
    gbar();

    // ---------- decision (uniform across grid) ----------
    {
        int bad = (tid < BSZ) ? g_bad[tid] : 0;
        if (__syncthreads_or(bad) == 0) return;   // fast path done
    }

    // ================= FALLBACK (certified-impossible, but exact) =================
    for (int i = gtid; i < BSZ * HDIM; i += gsz) {
        const float t = __bfloat162float(g_Hh[2][i]) + __bfloat162float(g_Hl[2][i]);
        g_D[i] = 1.0f - t * t;
    }
    for (int i = gtid; i < 2 * BSZ * NDIM; i += gsz) {
        const int z = i / (BSZ * NDIM), j = i - z * (BSZ * NDIM);
        __nv_bfloat16 h, l;
        split_bf16(g_fgk[z][j], h, l);
        g_fgh[z][j] = h; g_fgl[z][j] = l;
    }
    {
        float (*ts)[65] = reinterpret_cast<float(*)[65]>(smem);
        for (int t = bid; t < 128; t += gridDim.x) {
            if (t < 64)
                trans_tile(ts, Wk1, NDIM, (t >> 2) * 64, (t & 3) * 64, g_K1Th, g_K1Tl, HDIM);
            else {
                const int tt = t - 64;
                trans_tile(ts, Wk2, HDIM, (tt & 3) * 64, (tt >> 2) * 64, g_K2Th, g_K2Tl, NDIM);
            }
        }
    }
    gbar();
    gemm_phase(sb, 64, DecP3{});
    gbar();
    for (int i = gtid; i < 2 * BSZ * HDIM; i += gsz) {
        const int z = i / (BSZ * HDIM), j = i - z * (BSZ * HDIM);
        const float v = (g_P3p[z][0][j] + g_P3p[z][1][j]) * g_D[j];
        __nv_bfloat16 h, l;
        split_bf16(v, h, l);
        g_dvh[z][j] = h; g_dvl[z][j] = l;
    }
    gbar();
    gemm_phase(sb, 64, DecP4{});
    gbar();
    if (bid < BSZ) {
        const int b = bid, i = tid;
        const int idx = b * NDIM + i;
        float jfv = 0.f, jgv = 0.f;
#pragma unroll
        for (int s = 0; s < 8; s++) {
            jfv += g_P4p[0][s][idx];
            jgv += g_P4p[1][s][idx];
        }
        const float fv = g_fgk[0][idx];
        const float gv = g_fgk[1][idx];
        const float kv = g_fgk[2][idx];
        float kn2 = kv * kv, jf2 = jfv * jfv, dt = kv * jgv;
#pragma unroll
        for (int off = 16; off > 0; off >>= 1) {
            kn2 += __shfl_down_sync(0xffffffffu, kn2, off);
            jf2 += __shfl_down_sync(0xffffffffu, jf2, off);
            dt  += __shfl_down_sync(0xffffffffu, dt,  off);
        }
        const int warp = i >> 5, lane = i & 31;
        if (lane == 0) { red[warp] = kn2; red[8 + warp] = jf2; red[16 + warp] = dt; }
        __syncthreads();
        __shared__ float s_scale;
        if (i == 0) {
            float tkn2 = 0.f, tjf2 = 0.f, tdt = 0.f;
#pragma unroll
            for (int ww = 0; ww < 8; ww++) {
                tkn2 += red[ww]; tjf2 += red[8 + ww]; tdt += red[16 + ww];
            }
            const float kn   = sqrtf(tkn2);
            const float kn9  = tkn2 * tkn2 * tkn2 * tkn2 * kn;
            const float kn10 = kn9 * kn;
            const float c1 = sqrtf(tjf2) - ALPHA * kn9;
            const float c2 = tdt - BETA * kn10;
            s_scale = ((c1 > EPSC) || (c2 < -EPSC)) ? 0.5f : 1.0f;
        }
        __syncthreads();
        out[idx] = s_scale * (fv + gv);
    }
}

// inputs: 0:t 1:x 2:Wf1 3:bf1 4:Wf2 5:bf2 6:Wg1 7:bg1 8:Wg2 9:bg2 10:Wk1 11:bk1 12:Wk2 13:bk2
extern "C" void kernel_launch(void* const* d_in, const int* in_sizes, int n_in,
                              void* d_out, int out_size)
{
    const float* x   = (const float*)d_in[1];
    const float* Wf1 = (const float*)d_in[2];
    const float* bf1 = (const float*)d_in[3];
    const float* Wf2 = (const float*)d_in[4];
    const float* bf2 = (const float*)d_in[5];
    const float* Wg1 = (const float*)d_in[6];
    const float* bg1 = (const float*)d_in[7];
    const float* Wg2 = (const float*)d_in[8];
    const float* bg2 = (const float*)d_in[9];
    const float* Wk1 = (const float*)d_in[10];
    const float* bk1 = (const float*)d_in[11];
    const float* Wk2 = (const float*)d_in[12];
    const float* bk2 = (const float*)d_in[13];
    float* out = (float*)d_out;

    cudaFuncSetAttribute(fused_v2_kernel,
                         cudaFuncAttributeMaxDynamicSharedMemorySize, SMEM_TOTAL);

    int dev = 0, sms = 148;
    cudaGetDevice(&dev);
    cudaDeviceGetAttribute(&sms, cudaDevAttrMultiProcessorCount, dev);
    int occ = 1;
    cudaOccupancyMaxActiveBlocksPerMultiprocessor(&occ, fused_v2_kernel, 256, SMEM_TOTAL);
    if (occ < 1) occ = 1;
    if (occ > 2) occ = 2;
    int grid = sms * occ;
    if (grid < 160) grid = 160;   // fnorm needs blocks 96..159 (co-residency holds: 160 <= sms*1? guarded by occ>=1 on 148 SMs -> 160 blocks at occ>=2 requirement; occ is 2 for this config)

    fused_v2_kernel<<<grid, 256, SMEM_TOTAL>>>(x, Wf1, bf1, Wf2, bf2, Wg1, bg1,
                                               Wg2, bg2, Wk1, bk1, Wk2, bk2, out);
}